// round 5
// baseline (speedup 1.0000x reference)
#include <cuda_runtime.h>
#include <math.h>

// Problem dims
#define BB 64     // batch
#define TT 110    // timesteps
#define PP 64     // series
#define HH 256    // hidden
#define KK 16     // connections
#define LL 100    // nets seq length

typedef unsigned long long u64;

// Output layout (tuple concat, all f32):
//   pred   (P,B,L,1) : 409600  @ 0
//   logvar (B,H)     : 16384   @ 409600
//   mu     (B,H)     : 16384   @ 425984
//   mean   (B,P)     : 4096    @ 442368
//   disp   (B,P)     : 4096    @ 446464

__device__ float g_z[BB * HH];                       // latent z scratch
__device__ float g_WThh[(size_t)PP * HH * 768];      // 48MB: Whh_nets transposed [p][k][768]
__device__ float g_WTih[(size_t)PP * KK * 768];      // 3MB:  Wih_nets transposed [p][k][768]
__device__ float g_WTenc[606208];                    // encoder weights transposed

#define OFF_HHL  0        // W_hh_left^T  [256][768]
#define OFF_IHL  196608   // W_ih_left^T  [64][768]
#define OFF_IH1  245760   // W_ih_1^T     [256][768]
#define OFF_MU   442368   // W_mu^T       [256][256]
#define OFF_STD  507904   // W_std^T      [256][256]
#define OFF_MEAN 573440   // W_mean^T     [256][64]
#define OFF_DISP 589824   // W_disp^T     [256][64]

__device__ __forceinline__ u64 pk2(float x) {
    u64 r; asm("mov.b64 %0, {%1, %1};" : "=l"(r) : "f"(x)); return r;
}
__device__ __forceinline__ u64 ffma2(u64 a, u64 b, u64 c) {
    u64 d; asm("fma.rn.f32x2 %0, %1, %2, %3;" : "=l"(d) : "l"(a), "l"(b), "l"(c)); return d;
}
__device__ __forceinline__ void upk2(u64 a, float& lo, float& hi) {
    asm("mov.b64 {%0, %1}, %2;" : "=f"(lo), "=f"(hi) : "l"(a));
}
__device__ __forceinline__ float fsig(float x) {
    return __fdividef(1.0f, 1.0f + __expf(-x));
}
__device__ __forceinline__ float ftanh_(float x) {
    float e = __expf(fminf(fmaxf(2.0f * x, -80.0f), 80.0f));
    return __fdividef(e - 1.0f, e + 1.0f);
}

// ------------------------------------------------------------------
// Batched tiled transpose: in (Z, R, C) -> out (Z, C, R)
// ------------------------------------------------------------------
__global__ void transpose_k(const float* __restrict__ in, float* __restrict__ out,
                            int R, int C)
{
    __shared__ float tile[32][33];
    const size_t zoff = (size_t)blockIdx.z * R * C;
    in  += zoff;
    out += zoff;
    const int x = blockIdx.x * 32 + threadIdx.x;
    const int ybase = blockIdx.y * 32;
    #pragma unroll
    for (int j = threadIdx.y; j < 32; j += 8) {
        int y = ybase + j;
        if (x < C && y < R) tile[j][threadIdx.x] = in[(size_t)y * C + x];
    }
    __syncthreads();
    const int xo = ybase + threadIdx.x;
    const int yobase = blockIdx.x * 32;
    #pragma unroll
    for (int j = threadIdx.y; j < 32; j += 8) {
        int yo = yobase + j;
        if (yo < C && xo < R) out[(size_t)yo * R + xo] = tile[threadIdx.x][j];
    }
}

// ------------------------------------------------------------------
// Encoder: gru_left (10 steps) -> gru_1 (1 step, h0=0) -> heads + z
// ------------------------------------------------------------------
__global__ void __launch_bounds__(256) encoder_kernel(
    const float* __restrict__ X,
    const float* __restrict__ bih_l, const float* __restrict__ bhh_l,
    const float* __restrict__ bih1,  const float* __restrict__ bhh1,
    const float* __restrict__ bmu,   const float* __restrict__ bstd,
    const float* __restrict__ bmean, const float* __restrict__ bdisp,
    const float* __restrict__ z_noise,
    float* __restrict__ out_logvar, float* __restrict__ out_mu,
    float* __restrict__ out_mean,   float* __restrict__ out_disp)
{
    const int b = blockIdx.x;
    const int t = threadIdx.x;
    __shared__ float hs[HH];
    __shared__ float xs[PP];
    hs[t] = 0.0f;

    const float bir = bih_l[t]        + bhh_l[t];
    const float biz = bih_l[HH + t]   + bhh_l[HH + t];
    const float bin = bih_l[2*HH + t];
    const float bhn = bhh_l[2*HH + t];
    const float* __restrict__ Wh = g_WTenc + OFF_HHL;
    const float* __restrict__ Wi = g_WTenc + OFF_IHL;
    __syncthreads();

    for (int s = 0; s < 10; s++) {
        if (t < PP) xs[t] = X[((size_t)b * TT + s) * PP + t];
        __syncthreads();
        float ar = bir, az = biz, an = bin, gn = bhn;
        #pragma unroll 4
        for (int k = 0; k < HH; k++) {
            float hk = hs[k];
            ar += hk * Wh[k*768 + t];
            az += hk * Wh[k*768 + 256 + t];
            gn += hk * Wh[k*768 + 512 + t];
        }
        #pragma unroll 4
        for (int k = 0; k < PP; k++) {
            float xk = xs[k];
            ar += xk * Wi[k*768 + t];
            az += xk * Wi[k*768 + 256 + t];
            an += xk * Wi[k*768 + 512 + t];
        }
        float r  = fsig(ar);
        float zz = fsig(az);
        float n  = ftanh_(an + r * gn);
        float hnew = (1.0f - zz) * n + zz * hs[t];
        __syncthreads();
        hs[t] = hnew;
        __syncthreads();
    }

    {
        const float* __restrict__ W1 = g_WTenc + OFF_IH1;
        float ar = bih1[t]        + bhh1[t];
        float az = bih1[HH + t]   + bhh1[HH + t];
        float an = bih1[2*HH + t];
        float gn = bhh1[2*HH + t];
        #pragma unroll 4
        for (int k = 0; k < HH; k++) {
            float hk = hs[k];
            ar += hk * W1[k*768 + t];
            az += hk * W1[k*768 + 256 + t];
            an += hk * W1[k*768 + 512 + t];
        }
        float r  = fsig(ar);
        float zz = fsig(az);
        float n  = ftanh_(an + r * gn);
        float h1 = (1.0f - zz) * n;
        __syncthreads();
        hs[t] = h1;
        __syncthreads();
    }

    {
        float mu = bmu[t], lv = bstd[t];
        const float* __restrict__ Wm = g_WTenc + OFF_MU;
        const float* __restrict__ Ws = g_WTenc + OFF_STD;
        #pragma unroll 4
        for (int k = 0; k < HH; k++) {
            float hk = hs[k];
            mu += hk * Wm[k*256 + t];
            lv += hk * Ws[k*256 + t];
        }
        out_mu[b*HH + t]     = mu;
        out_logvar[b*HH + t] = lv;
        g_z[b*HH + t] = mu + expf(0.5f * lv) * z_noise[b*HH + t];

        if (t < PP) {
            float m = bmean[t], d = bdisp[t];
            const float* __restrict__ Wme = g_WTenc + OFF_MEAN;
            const float* __restrict__ Wd  = g_WTenc + OFF_DISP;
            #pragma unroll 4
            for (int k = 0; k < HH; k++) {
                float hk = hs[k];
                m += hk * Wme[k*64 + t];
                d += hk * Wd[k*64 + t];
            }
            m = expf(m);
            m = fminf(fmaxf(m, 1e-5f), 1e6f);
            d = log1pf(expf(d));
            d = fminf(fmaxf(d, 1e-4f), 1e4f);
            out_mean[b*PP + t] = m;
            out_disp[b*PP + t] = d;
        }
    }
}

// ------------------------------------------------------------------
// Per-series GRU nets: grid (64, 4), 512 threads, 2 CTAs/SM.
// Thread = 1 hidden unit x 8 batches (16 u64 accums -> ~62 regs).
// h/x/psum double-buffered: exactly ONE barrier per step.
// h stored k-major (hs2[buf][k][16b], stride 20) -> LDS.128 gives two
// f32x2 operands directly. Weights pre-transposed -> coalesced LDG.32.
// Per-warp k-rotation desyncs the post-barrier L2 burst.
// ------------------------------------------------------------------
#define HST 20                 // hs row stride (16 batches + 4 pad)
#define HSZ (HH * HST)

__global__ void __launch_bounds__(512, 2) nets_kernel(
    const float* __restrict__ X,
    const int*   __restrict__ conn_idx,
    const float* __restrict__ bih,   // (P, 768)
    const float* __restrict__ bhh,   // (P, 768)
    const float* __restrict__ Wlin,  // (P, 1, 256)
    const float* __restrict__ blin,  // (P, 1)
    float* __restrict__ pred)        // (P, B, L, 1)
{
    const int p    = blockIdx.x;
    const int b0c  = blockIdx.y * 16;
    const int tid  = threadIdx.x;
    const int g    = tid >> 8;        // batch-group 0/1 (8 batches each)
    const int t    = tid & 255;       // hidden unit
    const int g8   = g << 3;
    const int lane = tid & 31;
    const int wg   = (tid >> 5) & 7;  // warp within group
    const int rot  = ((tid >> 5) & 7) << 5;   // per-warp k rotation (0..224)

    __shared__ __align__(16) float hs2[2][HSZ];      // [buf][k][16b]
    __shared__ __align__(16) float xg2[2][KK * HST]; // [buf][k][16b]
    __shared__ float psum[2][2][8][8];               // [buf][g][warp][batch]
    __shared__ int   cidx[KK];

    if (tid < KK) cidx[tid] = conn_idx[p*KK + tid];
    for (int i = tid; i < KK*HST; i += 512) xg2[0][i] = 0.0f;  // step0 = zero row
    #pragma unroll
    for (int j = 0; j < 8; j++)
        hs2[0][t*HST + g8 + j] = g_z[(size_t)(b0c + g8 + j) * HH + t];

    const size_t pb = (size_t)p * 768;
    const u64 brc2 = pk2(bih[pb + t]       + bhh[pb + t]);
    const u64 bzc2 = pk2(bih[pb + 256 + t] + bhh[pb + 256 + t]);
    const u64 bin2 = pk2(bih[pb + 512 + t]);
    const u64 bhn2 = pk2(bhh[pb + 512 + t]);
    const float wl  = Wlin[(size_t)p * HH + t];
    const float blv = blin[p];
    const float* __restrict__ Wh = g_WThh + (size_t)p * HH * 768;  // [k][768]
    const float* __restrict__ Wi = g_WTih + (size_t)p * KK * 768;  // [k][768]

    __syncthreads();

    for (int l = 0; l < LL; l++) {
        const int cur = l & 1, nxt = cur ^ 1;

        // finalize pred for step l-1 (psum[nxt] was written last step)
        if (l > 0 && tid < 16) {
            const int gg = tid >> 3, jj = tid & 7;
            float s = 0.0f;
            #pragma unroll
            for (int w = 0; w < 8; w++) s += psum[nxt][gg][w][jj];
            pred[((size_t)(p*BB + b0c + (gg<<3) + jj)) * LL + (l-1)] = s + blv;
        }

        u64 ar2[4], az2[4], gi2[4], gh2[4];
        #pragma unroll
        for (int q = 0; q < 4; q++) { ar2[q]=brc2; az2[q]=bzc2; gi2[q]=bin2; gh2[q]=bhn2; }

        // input contribution (K = 16)
        #pragma unroll
        for (int k = 0; k < KK; k++) {
            const float* r_ = Wi + (size_t)k * 768;
            const u64 wr = pk2(r_[t]);
            const u64 wz = pk2(r_[256 + t]);
            const u64 wn = pk2(r_[512 + t]);
            const ulonglong2* hp =
                reinterpret_cast<const ulonglong2*>(&xg2[cur][k*HST + g8]);
            #pragma unroll
            for (int q = 0; q < 2; q++) {
                ulonglong2 hv = hp[q];
                ar2[2*q]   = ffma2(hv.x, wr, ar2[2*q]);
                az2[2*q]   = ffma2(hv.x, wz, az2[2*q]);
                gi2[2*q]   = ffma2(hv.x, wn, gi2[2*q]);
                ar2[2*q+1] = ffma2(hv.y, wr, ar2[2*q+1]);
                az2[2*q+1] = ffma2(hv.y, wz, az2[2*q+1]);
                gi2[2*q+1] = ffma2(hv.y, wn, gi2[2*q+1]);
            }
        }

        // hidden contribution (H = 256), per-warp rotated order
        #pragma unroll 1
        for (int kk = 0; kk < HH; kk += 4) {
            #pragma unroll
            for (int j = 0; j < 4; j++) {
                const int k = (kk + j + rot) & 255;
                const float* r_ = Wh + (size_t)k * 768;
                const u64 wr = pk2(r_[t]);
                const u64 wz = pk2(r_[256 + t]);
                const u64 wn = pk2(r_[512 + t]);
                const ulonglong2* hp =
                    reinterpret_cast<const ulonglong2*>(&hs2[cur][k*HST + g8]);
                #pragma unroll
                for (int q = 0; q < 2; q++) {
                    ulonglong2 hv = hp[q];
                    ar2[2*q]   = ffma2(hv.x, wr, ar2[2*q]);
                    az2[2*q]   = ffma2(hv.x, wz, az2[2*q]);
                    gh2[2*q]   = ffma2(hv.x, wn, gh2[2*q]);
                    ar2[2*q+1] = ffma2(hv.y, wr, ar2[2*q+1]);
                    az2[2*q+1] = ffma2(hv.y, wz, az2[2*q+1]);
                    gh2[2*q+1] = ffma2(hv.y, wn, gh2[2*q+1]);
                }
            }
        }

        // old h for the z-gate mix (reads cur buffer: safe, no barrier needed)
        float hold[8];
        #pragma unroll
        for (int j = 0; j < 2; j++) {
            float4 hv = *reinterpret_cast<const float4*>(&hs2[cur][t*HST + g8 + 4*j]);
            hold[4*j]   = hv.x; hold[4*j+1] = hv.y;
            hold[4*j+2] = hv.z; hold[4*j+3] = hv.w;
        }

        float hnew[8];
        #pragma unroll
        for (int q = 0; q < 4; q++) {
            float a0,a1,z0,z1,i0,i1,n0,n1;
            upk2(ar2[q], a0, a1);
            upk2(az2[q], z0, z1);
            upk2(gi2[q], i0, i1);
            upk2(gh2[q], n0, n1);
            float r0 = fsig(a0), r1 = fsig(a1);
            float zz0 = fsig(z0), zz1 = fsig(z1);
            float nn0 = ftanh_(i0 + r0 * n0);
            float nn1 = ftanh_(i1 + r1 * n1);
            hnew[2*q]   = (1.0f - zz0) * nn0 + zz0 * hold[2*q];
            hnew[2*q+1] = (1.0f - zz1) * nn1 + zz1 * hold[2*q+1];
        }

        // commit new hidden state to the next buffer (no conflict with readers)
        #pragma unroll
        for (int j = 0; j < 2; j++) {
            *reinterpret_cast<float4*>(&hs2[nxt][t*HST + g8 + 4*j]) =
                make_float4(hnew[4*j], hnew[4*j+1], hnew[4*j+2], hnew[4*j+3]);
        }

        // pred partials: warp-reduce relu(h).wl per batch into psum[cur]
        #pragma unroll
        for (int i = 0; i < 8; i++) {
            float v = fmaxf(hnew[i], 0.0f) * wl;
            v += __shfl_xor_sync(0xffffffffu, v, 16);
            v += __shfl_xor_sync(0xffffffffu, v, 8);
            v += __shfl_xor_sync(0xffffffffu, v, 4);
            v += __shfl_xor_sync(0xffffffffu, v, 2);
            v += __shfl_xor_sync(0xffffffffu, v, 1);
            if (lane == i) psum[cur][g][wg][i] = v;
        }

        // gather inputs for step l+1 into next buffer: X[:, 10+l, conn]
        if (l < LL - 1 && tid < 256) {
            int bb = tid >> 4, kk2 = tid & 15;
            xg2[nxt][kk2*HST + bb] =
                X[((size_t)(b0c + bb) * TT + (10 + l)) * PP + cidx[kk2]];
        }

        __syncthreads();   // ONE barrier: publishes hs2[nxt], xg2[nxt], psum[cur]
    }

    // finalize pred for the last step (psum[(LL-1)&1] = psum[1])
    if (tid < 16) {
        const int gg = tid >> 3, jj = tid & 7;
        float s = 0.0f;
        #pragma unroll
        for (int w = 0; w < 8; w++) s += psum[1][gg][w][jj];
        pred[((size_t)(p*BB + b0c + (gg<<3) + jj)) * LL + (LL-1)] = s + blv;
    }
}

extern "C" void kernel_launch(void* const* d_in, const int* in_sizes, int n_in,
                              void* d_out, int out_size)
{
    const float* X         = (const float*)d_in[0];
    const int*   conn_idx  = (const int*)  d_in[1];
    const float* W_ih_left = (const float*)d_in[2];
    const float* W_hh_left = (const float*)d_in[3];
    const float* b_ih_left = (const float*)d_in[4];
    const float* b_hh_left = (const float*)d_in[5];
    const float* W_ih_1    = (const float*)d_in[6];
    // d_in[7] = W_hh_1: unused (hidden state is 0 for gru_1's single step)
    const float* b_ih_1    = (const float*)d_in[8];
    const float* b_hh_1    = (const float*)d_in[9];
    const float* W_mu      = (const float*)d_in[10];
    const float* b_mu      = (const float*)d_in[11];
    const float* W_std     = (const float*)d_in[12];
    const float* b_std     = (const float*)d_in[13];
    const float* W_mean    = (const float*)d_in[14];
    const float* b_mean    = (const float*)d_in[15];
    const float* W_disp    = (const float*)d_in[16];
    const float* b_disp    = (const float*)d_in[17];
    const float* W_ih_nets = (const float*)d_in[18];
    const float* W_hh_nets = (const float*)d_in[19];
    const float* b_ih_nets = (const float*)d_in[20];
    const float* b_hh_nets = (const float*)d_in[21];
    const float* W_lin     = (const float*)d_in[22];
    const float* b_lin     = (const float*)d_in[23];
    const float* z_noise   = (const float*)d_in[24];

    float* out = (float*)d_out;
    float* pred       = out;
    float* out_logvar = out + 409600;
    float* out_mu     = out + 409600 + 16384;
    float* out_mean   = out + 409600 + 2*16384;
    float* out_disp   = out + 409600 + 2*16384 + 4096;

    float *wthh, *wtih, *wtenc;
    cudaGetSymbolAddress((void**)&wthh,  g_WThh);
    cudaGetSymbolAddress((void**)&wtih,  g_WTih);
    cudaGetSymbolAddress((void**)&wtenc, g_WTenc);

    dim3 tb(32, 8);
    transpose_k<<<dim3(8, 24, PP), tb>>>(W_hh_nets, wthh, 768, 256);
    transpose_k<<<dim3(1, 24, PP), tb>>>(W_ih_nets, wtih, 768, 16);
    transpose_k<<<dim3(8, 24, 1), tb>>>(W_hh_left, wtenc + OFF_HHL, 768, 256);
    transpose_k<<<dim3(2, 24, 1), tb>>>(W_ih_left, wtenc + OFF_IHL, 768, 64);
    transpose_k<<<dim3(8, 24, 1), tb>>>(W_ih_1,    wtenc + OFF_IH1, 768, 256);
    transpose_k<<<dim3(8, 8, 1),  tb>>>(W_mu,      wtenc + OFF_MU,  256, 256);
    transpose_k<<<dim3(8, 8, 1),  tb>>>(W_std,     wtenc + OFF_STD, 256, 256);
    transpose_k<<<dim3(8, 2, 1),  tb>>>(W_mean,    wtenc + OFF_MEAN, 64, 256);
    transpose_k<<<dim3(8, 2, 1),  tb>>>(W_disp,    wtenc + OFF_DISP, 64, 256);

    encoder_kernel<<<BB, 256>>>(
        X, b_ih_left, b_hh_left, b_ih_1, b_hh_1,
        b_mu, b_std, b_mean, b_disp, z_noise,
        out_logvar, out_mu, out_mean, out_disp);

    nets_kernel<<<dim3(PP, BB/16), 512>>>(
        X, conn_idx, b_ih_nets, b_hh_nets, W_lin, b_lin, pred);
}

// round 6
// speedup vs baseline: 1.8008x; 1.8008x over previous
#include <cuda_runtime.h>
#include <math.h>

// Problem dims
#define BB 64     // batch
#define TT 110    // timesteps
#define PP 64     // series
#define HH 256    // hidden
#define KK 16     // connections
#define LL 100    // nets seq length

typedef unsigned long long u64;

// Output layout (tuple concat, all f32):
//   pred   (P,B,L,1) : 409600  @ 0
//   logvar (B,H)     : 16384   @ 409600
//   mu     (B,H)     : 16384   @ 425984
//   mean   (B,P)     : 4096    @ 442368
//   disp   (B,P)     : 4096    @ 446464

__device__ float g_z[BB * HH];                       // latent z scratch
__device__ float g_WThh[(size_t)PP * HH * 768];      // 48MB: Whh_nets transposed [p][k][768]
__device__ float g_WTih[(size_t)PP * KK * 768];      // 3MB:  Wih_nets transposed [p][k][768]
__device__ float g_WTenc[606208];                    // encoder weights transposed

#define OFF_HHL  0        // W_hh_left^T  [256][768]
#define OFF_IHL  196608   // W_ih_left^T  [64][768]
#define OFF_IH1  245760   // W_ih_1^T     [256][768]
#define OFF_MU   442368   // W_mu^T       [256][256]
#define OFF_STD  507904   // W_std^T      [256][256]
#define OFF_MEAN 573440   // W_mean^T     [256][64]
#define OFF_DISP 589824   // W_disp^T     [256][64]

__device__ __forceinline__ u64 pk2(float x) {
    u64 r; asm("mov.b64 %0, {%1, %1};" : "=l"(r) : "f"(x)); return r;
}
__device__ __forceinline__ u64 ffma2(u64 a, u64 b, u64 c) {
    u64 d; asm("fma.rn.f32x2 %0, %1, %2, %3;" : "=l"(d) : "l"(a), "l"(b), "l"(c)); return d;
}
__device__ __forceinline__ void upk2(u64 a, float& lo, float& hi) {
    asm("mov.b64 {%0, %1}, %2;" : "=f"(lo), "=f"(hi) : "l"(a));
}
__device__ __forceinline__ float fsig(float x) {
    return __fdividef(1.0f, 1.0f + __expf(-x));
}
__device__ __forceinline__ float ftanh_(float x) {
    float e = __expf(fminf(fmaxf(2.0f * x, -80.0f), 80.0f));
    return __fdividef(e - 1.0f, e + 1.0f);
}

// ------------------------------------------------------------------
// Batched tiled transpose: in (Z, R, C) -> out (Z, C, R)
// ------------------------------------------------------------------
__global__ void transpose_k(const float* __restrict__ in, float* __restrict__ out,
                            int R, int C)
{
    __shared__ float tile[32][33];
    const size_t zoff = (size_t)blockIdx.z * R * C;
    in  += zoff;
    out += zoff;
    const int x = blockIdx.x * 32 + threadIdx.x;
    const int ybase = blockIdx.y * 32;
    #pragma unroll
    for (int j = threadIdx.y; j < 32; j += 8) {
        int y = ybase + j;
        if (x < C && y < R) tile[j][threadIdx.x] = in[(size_t)y * C + x];
    }
    __syncthreads();
    const int xo = ybase + threadIdx.x;
    const int yobase = blockIdx.x * 32;
    #pragma unroll
    for (int j = threadIdx.y; j < 32; j += 8) {
        int yo = yobase + j;
        if (yo < C && xo < R) out[(size_t)yo * R + xo] = tile[threadIdx.x][j];
    }
}

// Multi-matrix transpose: blockIdx.z selects one of 6 matrices
struct EncT {
    const float* in[6];
    float*       out[6];
    int          R[6];
    int          C[6];
};
__global__ void transpose_multi(EncT e)
{
    __shared__ float tile[32][33];
    const int m = blockIdx.z;
    const float* __restrict__ in = e.in[m];
    float* __restrict__ out = e.out[m];
    const int R = e.R[m], C = e.C[m];
    const int x = blockIdx.x * 32 + threadIdx.x;
    const int ybase = blockIdx.y * 32;
    #pragma unroll
    for (int j = threadIdx.y; j < 32; j += 8) {
        int y = ybase + j;
        if (x < C && y < R) tile[j][threadIdx.x] = in[(size_t)y * C + x];
    }
    __syncthreads();
    const int xo = ybase + threadIdx.x;
    const int yobase = blockIdx.x * 32;
    #pragma unroll
    for (int j = threadIdx.y; j < 32; j += 8) {
        int yo = yobase + j;
        if (yo < C && xo < R) out[(size_t)yo * R + xo] = tile[threadIdx.x][j];
    }
}

// ------------------------------------------------------------------
// Encoder: gru_left (10 steps) -> gru_1 (1 step, h0=0) -> heads + z
// ------------------------------------------------------------------
__global__ void __launch_bounds__(256) encoder_kernel(
    const float* __restrict__ X,
    const float* __restrict__ bih_l, const float* __restrict__ bhh_l,
    const float* __restrict__ bih1,  const float* __restrict__ bhh1,
    const float* __restrict__ bmu,   const float* __restrict__ bstd,
    const float* __restrict__ bmean, const float* __restrict__ bdisp,
    const float* __restrict__ z_noise,
    float* __restrict__ out_logvar, float* __restrict__ out_mu,
    float* __restrict__ out_mean,   float* __restrict__ out_disp)
{
    const int b = blockIdx.x;
    const int t = threadIdx.x;
    __shared__ float hs[HH];
    __shared__ float xs[PP];
    hs[t] = 0.0f;

    const float bir = bih_l[t]        + bhh_l[t];
    const float biz = bih_l[HH + t]   + bhh_l[HH + t];
    const float bin = bih_l[2*HH + t];
    const float bhn = bhh_l[2*HH + t];
    const float* __restrict__ Wh = g_WTenc + OFF_HHL;
    const float* __restrict__ Wi = g_WTenc + OFF_IHL;
    __syncthreads();

    for (int s = 0; s < 10; s++) {
        if (t < PP) xs[t] = X[((size_t)b * TT + s) * PP + t];
        __syncthreads();
        float ar = bir, az = biz, an = bin, gn = bhn;
        #pragma unroll 4
        for (int k = 0; k < HH; k++) {
            float hk = hs[k];
            ar += hk * Wh[k*768 + t];
            az += hk * Wh[k*768 + 256 + t];
            gn += hk * Wh[k*768 + 512 + t];
        }
        #pragma unroll 4
        for (int k = 0; k < PP; k++) {
            float xk = xs[k];
            ar += xk * Wi[k*768 + t];
            az += xk * Wi[k*768 + 256 + t];
            an += xk * Wi[k*768 + 512 + t];
        }
        float r  = fsig(ar);
        float zz = fsig(az);
        float n  = ftanh_(an + r * gn);
        float hnew = (1.0f - zz) * n + zz * hs[t];
        __syncthreads();
        hs[t] = hnew;
        __syncthreads();
    }

    {
        const float* __restrict__ W1 = g_WTenc + OFF_IH1;
        float ar = bih1[t]        + bhh1[t];
        float az = bih1[HH + t]   + bhh1[HH + t];
        float an = bih1[2*HH + t];
        float gn = bhh1[2*HH + t];
        #pragma unroll 4
        for (int k = 0; k < HH; k++) {
            float hk = hs[k];
            ar += hk * W1[k*768 + t];
            az += hk * W1[k*768 + 256 + t];
            an += hk * W1[k*768 + 512 + t];
        }
        float r  = fsig(ar);
        float zz = fsig(az);
        float n  = ftanh_(an + r * gn);
        float h1 = (1.0f - zz) * n;
        __syncthreads();
        hs[t] = h1;
        __syncthreads();
    }

    {
        float mu = bmu[t], lv = bstd[t];
        const float* __restrict__ Wm = g_WTenc + OFF_MU;
        const float* __restrict__ Ws = g_WTenc + OFF_STD;
        #pragma unroll 4
        for (int k = 0; k < HH; k++) {
            float hk = hs[k];
            mu += hk * Wm[k*256 + t];
            lv += hk * Ws[k*256 + t];
        }
        out_mu[b*HH + t]     = mu;
        out_logvar[b*HH + t] = lv;
        g_z[b*HH + t] = mu + expf(0.5f * lv) * z_noise[b*HH + t];

        if (t < PP) {
            float m = bmean[t], d = bdisp[t];
            const float* __restrict__ Wme = g_WTenc + OFF_MEAN;
            const float* __restrict__ Wd  = g_WTenc + OFF_DISP;
            #pragma unroll 4
            for (int k = 0; k < HH; k++) {
                float hk = hs[k];
                m += hk * Wme[k*64 + t];
                d += hk * Wd[k*64 + t];
            }
            m = expf(m);
            m = fminf(fmaxf(m, 1e-5f), 1e6f);
            d = log1pf(expf(d));
            d = fminf(fmaxf(d, 1e-4f), 1e4f);
            out_mean[b*PP + t] = m;
            out_disp[b*PP + t] = d;
        }
    }
}

// ------------------------------------------------------------------
// Per-series GRU nets: grid (64, 2), 512 threads, 1 CTA/SM (R4 config).
// Thread = 1 hidden unit x 16 batches (32 u64 accums).
// h/x/psum double-buffered -> ONE barrier per step.
// Thread keeps its own h in registers (hprev) across steps: no strided
// LDS reload for the z-gate mix.
// h stored k-major (hs[buf][k][32b], stride 36) -> LDS.128 = two f32x2
// operands. Weights pre-transposed -> coalesced LDG.32.
// ------------------------------------------------------------------
#define HST 36                 // hs row stride (32 batches + 4 pad)
#define HS_BUF (HH * HST)      // 9216 floats per buffer
#define XG_BUF (KK * HST)      // 576 floats per buffer
#define PS_BUF 256             // psum floats per buffer (2 g * 8 w * 16 b)

extern __shared__ float s_mem[];

__global__ void __launch_bounds__(512, 1) nets_kernel(
    const float* __restrict__ X,
    const int*   __restrict__ conn_idx,
    const float* __restrict__ bih,   // (P, 768)
    const float* __restrict__ bhh,   // (P, 768)
    const float* __restrict__ Wlin,  // (P, 1, 256)
    const float* __restrict__ blin,  // (P, 1)
    float* __restrict__ pred)        // (P, B, L, 1)
{
    const int p    = blockIdx.x;
    const int b0c  = blockIdx.y * 32;
    const int tid  = threadIdx.x;
    const int g    = tid >> 8;        // batch-group 0/1 (16 batches each)
    const int t    = tid & 255;       // hidden unit
    const int g16  = g << 4;
    const int lane = tid & 31;
    const int wg   = (tid >> 5) & 7;  // warp within group

    float* hs   = s_mem;                        // [2][HS_BUF]
    float* xg   = s_mem + 2*HS_BUF;             // [2][XG_BUF]
    float* ps   = s_mem + 2*HS_BUF + 2*XG_BUF;  // [2][PS_BUF] layout [g][w][16]
    int*   cidx = (int*)(ps + 2*PS_BUF);        // [KK]

    if (tid < KK) cidx[tid] = conn_idx[p*KK + tid];
    for (int i = tid; i < XG_BUF; i += 512) xg[i] = 0.0f;   // step0 = zero row

    // init h: registers + SMEM buffer 0
    float hprev[16];
    #pragma unroll
    for (int j = 0; j < 16; j++) {
        float v = g_z[(size_t)(b0c + g16 + j) * HH + t];
        hprev[j] = v;
        hs[t*HST + g16 + j] = v;
    }

    const size_t pb = (size_t)p * 768;
    const u64 brc2 = pk2(bih[pb + t]       + bhh[pb + t]);
    const u64 bzc2 = pk2(bih[pb + 256 + t] + bhh[pb + 256 + t]);
    const u64 bin2 = pk2(bih[pb + 512 + t]);
    const u64 bhn2 = pk2(bhh[pb + 512 + t]);
    const float wl  = Wlin[(size_t)p * HH + t];
    const float blv = blin[p];
    const float* __restrict__ Whp = g_WThh + (size_t)p * HH * 768 + t;  // [k][768]
    const float* __restrict__ Wip = g_WTih + (size_t)p * KK * 768 + t;  // [k][768]

    __syncthreads();

    for (int l = 0; l < LL; l++) {
        const int cur = l & 1, nxt = cur ^ 1;
        const float* hs_c = hs + cur*HS_BUF;
        float*       hs_n = hs + nxt*HS_BUF;
        const float* xg_c = xg + cur*XG_BUF;
        float*       xg_n = xg + nxt*XG_BUF;

        // finalize pred for step l-1 (psum[nxt buf] was written last step)
        if (l > 0 && tid < 32) {
            const int gg = tid >> 4, jj = tid & 15;
            const float* pp_ = ps + nxt*PS_BUF + gg*128;
            float s = 0.0f;
            #pragma unroll
            for (int w = 0; w < 8; w++) s += pp_[w*16 + jj];
            pred[((size_t)(p*BB + b0c + (gg<<4) + jj)) * LL + (l-1)] = s + blv;
        }

        u64 ar2[8], az2[8], gi2[8], gh2[8];
        #pragma unroll
        for (int q = 0; q < 8; q++) { ar2[q]=brc2; az2[q]=bzc2; gi2[q]=bin2; gh2[q]=bhn2; }

        // input contribution (K = 16)
        #pragma unroll
        for (int k = 0; k < KK; k++) {
            const float* r_ = Wip + (size_t)k * 768;
            const u64 wr = pk2(r_[0]);
            const u64 wz = pk2(r_[256]);
            const u64 wn = pk2(r_[512]);
            const ulonglong2* hp =
                reinterpret_cast<const ulonglong2*>(xg_c + k*HST + g16);
            #pragma unroll
            for (int q = 0; q < 4; q++) {
                ulonglong2 hv = hp[q];
                ar2[2*q]   = ffma2(hv.x, wr, ar2[2*q]);
                az2[2*q]   = ffma2(hv.x, wz, az2[2*q]);
                gi2[2*q]   = ffma2(hv.x, wn, gi2[2*q]);
                ar2[2*q+1] = ffma2(hv.y, wr, ar2[2*q+1]);
                az2[2*q+1] = ffma2(hv.y, wz, az2[2*q+1]);
                gi2[2*q+1] = ffma2(hv.y, wn, gi2[2*q+1]);
            }
        }

        // hidden contribution (H = 256) — the hot loop
        #pragma unroll 1
        for (int kk = 0; kk < HH; kk += 4) {
            #pragma unroll
            for (int j = 0; j < 4; j++) {
                const int k = kk + j;
                const float* r_ = Whp + (size_t)k * 768;
                const u64 wr = pk2(r_[0]);
                const u64 wz = pk2(r_[256]);
                const u64 wn = pk2(r_[512]);
                const ulonglong2* hp =
                    reinterpret_cast<const ulonglong2*>(hs_c + k*HST + g16);
                #pragma unroll
                for (int q = 0; q < 4; q++) {
                    ulonglong2 hv = hp[q];
                    ar2[2*q]   = ffma2(hv.x, wr, ar2[2*q]);
                    az2[2*q]   = ffma2(hv.x, wz, az2[2*q]);
                    gh2[2*q]   = ffma2(hv.x, wn, gh2[2*q]);
                    ar2[2*q+1] = ffma2(hv.y, wr, ar2[2*q+1]);
                    az2[2*q+1] = ffma2(hv.y, wz, az2[2*q+1]);
                    gh2[2*q+1] = ffma2(hv.y, wn, gh2[2*q+1]);
                }
            }
        }

        // gates -> new hidden (old h comes from registers: hprev)
        #pragma unroll
        for (int q = 0; q < 8; q++) {
            float a0,a1,z0,z1,i0,i1,n0,n1;
            upk2(ar2[q], a0, a1);
            upk2(az2[q], z0, z1);
            upk2(gi2[q], i0, i1);
            upk2(gh2[q], n0, n1);
            float r0 = fsig(a0), r1 = fsig(a1);
            float zz0 = fsig(z0), zz1 = fsig(z1);
            float nn0 = ftanh_(i0 + r0 * n0);
            float nn1 = ftanh_(i1 + r1 * n1);
            hprev[2*q]   = (1.0f - zz0) * nn0 + zz0 * hprev[2*q];
            hprev[2*q+1] = (1.0f - zz1) * nn1 + zz1 * hprev[2*q+1];
        }

        // commit new hidden state to next buffer
        #pragma unroll
        for (int j = 0; j < 4; j++) {
            *reinterpret_cast<float4*>(hs_n + t*HST + g16 + 4*j) =
                make_float4(hprev[4*j], hprev[4*j+1], hprev[4*j+2], hprev[4*j+3]);
        }

        // pred partials: warp-reduce relu(h).wl per batch into psum[cur]
        #pragma unroll
        for (int i = 0; i < 16; i++) {
            float v = fmaxf(hprev[i], 0.0f) * wl;
            v += __shfl_xor_sync(0xffffffffu, v, 16);
            v += __shfl_xor_sync(0xffffffffu, v, 8);
            v += __shfl_xor_sync(0xffffffffu, v, 4);
            v += __shfl_xor_sync(0xffffffffu, v, 2);
            v += __shfl_xor_sync(0xffffffffu, v, 1);
            if (lane == i) ps[cur*PS_BUF + g*128 + wg*16 + i] = v;
        }

        // gather inputs for step l+1 into next buffer: X[:, 10+l, conn]
        if (l < LL - 1) {
            int bb = tid >> 4, kk2 = tid & 15;
            xg_n[kk2*HST + bb] =
                X[((size_t)(b0c + bb) * TT + (10 + l)) * PP + cidx[kk2]];
        }

        __syncthreads();   // ONE barrier: publishes hs[nxt], xg[nxt], psum[cur]
    }

    // finalize pred for the last step (LL-1 is odd -> psum buffer 1)
    if (tid < 32) {
        const int gg = tid >> 4, jj = tid & 15;
        const float* pp_ = ps + 1*PS_BUF + gg*128;
        float s = 0.0f;
        #pragma unroll
        for (int w = 0; w < 8; w++) s += pp_[w*16 + jj];
        pred[((size_t)(p*BB + b0c + (gg<<4) + jj)) * LL + (LL-1)] = s + blv;
    }
}

extern "C" void kernel_launch(void* const* d_in, const int* in_sizes, int n_in,
                              void* d_out, int out_size)
{
    const float* X         = (const float*)d_in[0];
    const int*   conn_idx  = (const int*)  d_in[1];
    const float* W_ih_left = (const float*)d_in[2];
    const float* W_hh_left = (const float*)d_in[3];
    const float* b_ih_left = (const float*)d_in[4];
    const float* b_hh_left = (const float*)d_in[5];
    const float* W_ih_1    = (const float*)d_in[6];
    // d_in[7] = W_hh_1: unused (hidden state is 0 for gru_1's single step)
    const float* b_ih_1    = (const float*)d_in[8];
    const float* b_hh_1    = (const float*)d_in[9];
    const float* W_mu      = (const float*)d_in[10];
    const float* b_mu      = (const float*)d_in[11];
    const float* W_std     = (const float*)d_in[12];
    const float* b_std     = (const float*)d_in[13];
    const float* W_mean    = (const float*)d_in[14];
    const float* b_mean    = (const float*)d_in[15];
    const float* W_disp    = (const float*)d_in[16];
    const float* b_disp    = (const float*)d_in[17];
    const float* W_ih_nets = (const float*)d_in[18];
    const float* W_hh_nets = (const float*)d_in[19];
    const float* b_ih_nets = (const float*)d_in[20];
    const float* b_hh_nets = (const float*)d_in[21];
    const float* W_lin     = (const float*)d_in[22];
    const float* b_lin     = (const float*)d_in[23];
    const float* z_noise   = (const float*)d_in[24];

    float* out = (float*)d_out;
    float* pred       = out;
    float* out_logvar = out + 409600;
    float* out_mu     = out + 409600 + 16384;
    float* out_mean   = out + 409600 + 2*16384;
    float* out_disp   = out + 409600 + 2*16384 + 4096;

    float *wthh, *wtih, *wtenc;
    cudaGetSymbolAddress((void**)&wthh,  g_WThh);
    cudaGetSymbolAddress((void**)&wtih,  g_WTih);
    cudaGetSymbolAddress((void**)&wtenc, g_WTenc);

    // dynamic SMEM for nets: 2 h buffers + 2 x buffers + 2 psum + cidx
    const int smem_bytes = (2*HS_BUF + 2*XG_BUF + 2*PS_BUF) * 4 + KK * 4;
    cudaFuncSetAttribute(nets_kernel,
                         cudaFuncAttributeMaxDynamicSharedMemorySize, smem_bytes);

    dim3 tb(32, 8);
    // Exactly 6 launches so ncu (-s 5 -c 1) profiles nets_kernel.
    transpose_k<<<dim3(8, 24, PP), tb>>>(W_hh_nets, wthh, 768, 256);   // 0
    transpose_k<<<dim3(1, 24, PP), tb>>>(W_ih_nets, wtih, 768, 16);    // 1
    transpose_k<<<dim3(8, 24, 1),  tb>>>(W_hh_left, wtenc + OFF_HHL, 768, 256); // 2

    EncT e;                                                             // 3
    e.in[0] = W_ih_left; e.out[0] = wtenc + OFF_IHL;  e.R[0] = 768; e.C[0] = 64;
    e.in[1] = W_ih_1;    e.out[1] = wtenc + OFF_IH1;  e.R[1] = 768; e.C[1] = 256;
    e.in[2] = W_mu;      e.out[2] = wtenc + OFF_MU;   e.R[2] = 256; e.C[2] = 256;
    e.in[3] = W_std;     e.out[3] = wtenc + OFF_STD;  e.R[3] = 256; e.C[3] = 256;
    e.in[4] = W_mean;    e.out[4] = wtenc + OFF_MEAN; e.R[4] = 64;  e.C[4] = 256;
    e.in[5] = W_disp;    e.out[5] = wtenc + OFF_DISP; e.R[5] = 64;  e.C[5] = 256;
    transpose_multi<<<dim3(8, 24, 6), tb>>>(e);

    encoder_kernel<<<BB, 256>>>(                                        // 4
        X, b_ih_left, b_hh_left, b_ih_1, b_hh_1,
        b_mu, b_std, b_mean, b_disp, z_noise,
        out_logvar, out_mu, out_mean, out_disp);

    nets_kernel<<<dim3(PP, BB/32), 512, smem_bytes>>>(                  // 5
        X, conn_idx, b_ih_nets, b_hh_nets, W_lin, b_lin, pred);
}

// round 7
// speedup vs baseline: 1.8452x; 1.0247x over previous
#include <cuda_runtime.h>
#include <math.h>

// Problem dims
#define BB 64     // batch
#define TT 110    // timesteps
#define PP 64     // series
#define HH 256    // hidden
#define KK 16     // connections
#define LL 100    // nets seq length

typedef unsigned long long u64;

// Output layout (tuple concat, all f32):
//   pred   (P,B,L,1) : 409600  @ 0
//   logvar (B,H)     : 16384   @ 409600
//   mu     (B,H)     : 16384   @ 425984
//   mean   (B,P)     : 4096    @ 442368
//   disp   (B,P)     : 4096    @ 446464

__device__ float g_z[BB * HH];                        // latent z scratch
__device__ float g_Wf4[(size_t)PP * HH * HH * 4];     // 64MB: Whh_nets fused [p][k][t][{r,z,n,pad}]
__device__ float g_Wif4[(size_t)PP * KK * HH * 4];    // 4MB:  Wih_nets fused [p][k][t][{r,z,n,pad}]
__device__ float g_WTenc[606208];                     // encoder weights transposed

#define OFF_HHL  0        // W_hh_left^T  [256][768]
#define OFF_IHL  196608   // W_ih_left^T  [64][768]
#define OFF_IH1  245760   // W_ih_1^T     [256][768]
#define OFF_MU   442368   // W_mu^T       [256][256]
#define OFF_STD  507904   // W_std^T      [256][256]
#define OFF_MEAN 573440   // W_mean^T     [256][64]
#define OFF_DISP 589824   // W_disp^T     [256][64]

__device__ __forceinline__ u64 pk2(float x) {
    u64 r; asm("mov.b64 %0, {%1, %1};" : "=l"(r) : "f"(x)); return r;
}
__device__ __forceinline__ u64 ffma2(u64 a, u64 b, u64 c) {
    u64 d; asm("fma.rn.f32x2 %0, %1, %2, %3;" : "=l"(d) : "l"(a), "l"(b), "l"(c)); return d;
}
__device__ __forceinline__ void upk2(u64 a, float& lo, float& hi) {
    asm("mov.b64 {%0, %1}, %2;" : "=f"(lo), "=f"(hi) : "l"(a));
}
__device__ __forceinline__ float fsig(float x) {
    return __fdividef(1.0f, 1.0f + __expf(-x));
}
__device__ __forceinline__ float ftanh_(float x) {
    float e = __expf(fminf(fmaxf(2.0f * x, -80.0f), 80.0f));
    return __fdividef(e - 1.0f, e + 1.0f);
}

// ------------------------------------------------------------------
// Repack Whh_nets (P,768,256) -> fused [p][k][t][{r,z,n,0}]
// thread.x = k (coalesced reads); blockIdx.y = t; blockIdx.z = p
// ------------------------------------------------------------------
__global__ void repack_hh(const float* __restrict__ in, float* __restrict__ out)
{
    const int p = blockIdx.z, t = blockIdx.y, k = threadIdx.x;
    const float* W = in + (size_t)p * 768 * HH;
    float4 v;
    v.x = W[(size_t)(0*HH + t) * HH + k];
    v.y = W[(size_t)(1*HH + t) * HH + k];
    v.z = W[(size_t)(2*HH + t) * HH + k];
    v.w = 0.0f;
    reinterpret_cast<float4*>(out)[(((size_t)p * HH + k) * HH) + t] = v;
}

// Repack Wih_nets (P,768,16) -> fused [p][k][t][{r,z,n,0}]
// thread.x = t (coalesced writes); loop k; blockIdx.x = p
__global__ void repack_ih(const float* __restrict__ in, float* __restrict__ out)
{
    const int p = blockIdx.x, t = threadIdx.x;
    const float* W = in + (size_t)p * 768 * KK;
    #pragma unroll
    for (int k = 0; k < KK; k++) {
        float4 v;
        v.x = W[(size_t)(0*HH + t) * KK + k];
        v.y = W[(size_t)(1*HH + t) * KK + k];
        v.z = W[(size_t)(2*HH + t) * KK + k];
        v.w = 0.0f;
        reinterpret_cast<float4*>(out)[(((size_t)p * KK + k) * HH) + t] = v;
    }
}

// ------------------------------------------------------------------
// Batched tiled transpose: in (Z, R, C) -> out (Z, C, R)
// ------------------------------------------------------------------
__global__ void transpose_k(const float* __restrict__ in, float* __restrict__ out,
                            int R, int C)
{
    __shared__ float tile[32][33];
    const size_t zoff = (size_t)blockIdx.z * R * C;
    in  += zoff;
    out += zoff;
    const int x = blockIdx.x * 32 + threadIdx.x;
    const int ybase = blockIdx.y * 32;
    #pragma unroll
    for (int j = threadIdx.y; j < 32; j += 8) {
        int y = ybase + j;
        if (x < C && y < R) tile[j][threadIdx.x] = in[(size_t)y * C + x];
    }
    __syncthreads();
    const int xo = ybase + threadIdx.x;
    const int yobase = blockIdx.x * 32;
    #pragma unroll
    for (int j = threadIdx.y; j < 32; j += 8) {
        int yo = yobase + j;
        if (yo < C && xo < R) out[(size_t)yo * R + xo] = tile[threadIdx.x][j];
    }
}

// Multi-matrix transpose: blockIdx.z selects one of 6 matrices
struct EncT {
    const float* in[6];
    float*       out[6];
    int          R[6];
    int          C[6];
};
__global__ void transpose_multi(EncT e)
{
    __shared__ float tile[32][33];
    const int m = blockIdx.z;
    const float* __restrict__ in = e.in[m];
    float* __restrict__ out = e.out[m];
    const int R = e.R[m], C = e.C[m];
    const int x = blockIdx.x * 32 + threadIdx.x;
    const int ybase = blockIdx.y * 32;
    #pragma unroll
    for (int j = threadIdx.y; j < 32; j += 8) {
        int y = ybase + j;
        if (x < C && y < R) tile[j][threadIdx.x] = in[(size_t)y * C + x];
    }
    __syncthreads();
    const int xo = ybase + threadIdx.x;
    const int yobase = blockIdx.x * 32;
    #pragma unroll
    for (int j = threadIdx.y; j < 32; j += 8) {
        int yo = yobase + j;
        if (yo < C && xo < R) out[(size_t)yo * R + xo] = tile[threadIdx.x][j];
    }
}

// ------------------------------------------------------------------
// Encoder: gru_left (10 steps) -> gru_1 (1 step, h0=0) -> heads + z
// ------------------------------------------------------------------
__global__ void __launch_bounds__(256) encoder_kernel(
    const float* __restrict__ X,
    const float* __restrict__ bih_l, const float* __restrict__ bhh_l,
    const float* __restrict__ bih1,  const float* __restrict__ bhh1,
    const float* __restrict__ bmu,   const float* __restrict__ bstd,
    const float* __restrict__ bmean, const float* __restrict__ bdisp,
    const float* __restrict__ z_noise,
    float* __restrict__ out_logvar, float* __restrict__ out_mu,
    float* __restrict__ out_mean,   float* __restrict__ out_disp)
{
    const int b = blockIdx.x;
    const int t = threadIdx.x;
    __shared__ float hs[HH];
    __shared__ float xs[PP];
    hs[t] = 0.0f;

    const float bir = bih_l[t]        + bhh_l[t];
    const float biz = bih_l[HH + t]   + bhh_l[HH + t];
    const float bin = bih_l[2*HH + t];
    const float bhn = bhh_l[2*HH + t];
    const float* __restrict__ Wh = g_WTenc + OFF_HHL;
    const float* __restrict__ Wi = g_WTenc + OFF_IHL;
    __syncthreads();

    for (int s = 0; s < 10; s++) {
        if (t < PP) xs[t] = X[((size_t)b * TT + s) * PP + t];
        __syncthreads();
        float ar = bir, az = biz, an = bin, gn = bhn;
        #pragma unroll 4
        for (int k = 0; k < HH; k++) {
            float hk = hs[k];
            ar += hk * Wh[k*768 + t];
            az += hk * Wh[k*768 + 256 + t];
            gn += hk * Wh[k*768 + 512 + t];
        }
        #pragma unroll 4
        for (int k = 0; k < PP; k++) {
            float xk = xs[k];
            ar += xk * Wi[k*768 + t];
            az += xk * Wi[k*768 + 256 + t];
            an += xk * Wi[k*768 + 512 + t];
        }
        float r  = fsig(ar);
        float zz = fsig(az);
        float n  = ftanh_(an + r * gn);
        float hnew = (1.0f - zz) * n + zz * hs[t];
        __syncthreads();
        hs[t] = hnew;
        __syncthreads();
    }

    {
        const float* __restrict__ W1 = g_WTenc + OFF_IH1;
        float ar = bih1[t]        + bhh1[t];
        float az = bih1[HH + t]   + bhh1[HH + t];
        float an = bih1[2*HH + t];
        float gn = bhh1[2*HH + t];
        #pragma unroll 4
        for (int k = 0; k < HH; k++) {
            float hk = hs[k];
            ar += hk * W1[k*768 + t];
            az += hk * W1[k*768 + 256 + t];
            an += hk * W1[k*768 + 512 + t];
        }
        float r  = fsig(ar);
        float zz = fsig(az);
        float n  = ftanh_(an + r * gn);
        float h1 = (1.0f - zz) * n;
        __syncthreads();
        hs[t] = h1;
        __syncthreads();
    }

    {
        float mu = bmu[t], lv = bstd[t];
        const float* __restrict__ Wm = g_WTenc + OFF_MU;
        const float* __restrict__ Ws = g_WTenc + OFF_STD;
        #pragma unroll 4
        for (int k = 0; k < HH; k++) {
            float hk = hs[k];
            mu += hk * Wm[k*256 + t];
            lv += hk * Ws[k*256 + t];
        }
        out_mu[b*HH + t]     = mu;
        out_logvar[b*HH + t] = lv;
        g_z[b*HH + t] = mu + expf(0.5f * lv) * z_noise[b*HH + t];

        if (t < PP) {
            float m = bmean[t], d = bdisp[t];
            const float* __restrict__ Wme = g_WTenc + OFF_MEAN;
            const float* __restrict__ Wd  = g_WTenc + OFF_DISP;
            #pragma unroll 4
            for (int k = 0; k < HH; k++) {
                float hk = hs[k];
                m += hk * Wme[k*64 + t];
                d += hk * Wd[k*64 + t];
            }
            m = expf(m);
            m = fminf(fmaxf(m, 1e-5f), 1e6f);
            d = log1pf(expf(d));
            d = fminf(fmaxf(d, 1e-4f), 1e4f);
            out_mean[b*PP + t] = m;
            out_disp[b*PP + t] = d;
        }
    }
}

// ------------------------------------------------------------------
// Per-series GRU nets: grid (64, 2), 512 threads, R4 structure.
// Thread = 1 hidden unit x 16 batches (32 u64 accums).
// Fused weight layout: ONE LDG.128 per k gives (wr,wz,wn).
// h stored k-major (hs2[k][32b], stride 36) -> LDS.128 = two f32x2
// operands. Two barriers per step (known-good R4 schedule).
// ------------------------------------------------------------------
#define BT 16
#define HST 36                 // hs row stride (32 batches + 4 pad)

__global__ void __launch_bounds__(512, 1) nets_kernel(
    const float* __restrict__ X,
    const int*   __restrict__ conn_idx,
    const float* __restrict__ bih,   // (P, 768)
    const float* __restrict__ bhh,   // (P, 768)
    const float* __restrict__ Wlin,  // (P, 1, 256)
    const float* __restrict__ blin,  // (P, 1)
    float* __restrict__ pred)        // (P, B, L, 1)
{
    const int p    = blockIdx.x;
    const int b0c  = blockIdx.y * 32;
    const int tid  = threadIdx.x;
    const int g    = tid >> 8;        // batch-group 0/1 (16 batches each)
    const int t    = tid & 255;       // hidden unit
    const int g16  = g << 4;
    const int lane = tid & 31;
    const int wg   = (tid >> 5) & 7;  // warp within group

    __shared__ __align__(16) float hs2[HH * HST];   // [k][32b]
    __shared__ __align__(16) float xg2[KK * HST];   // [k][32b]
    __shared__ float psum[2][8][16];
    __shared__ int   cidx[KK];

    if (tid < KK) cidx[tid] = conn_idx[p*KK + tid];
    for (int i = tid; i < KK*HST; i += 512) xg2[i] = 0.0f;
    #pragma unroll
    for (int j = 0; j < BT; j++)
        hs2[t*HST + g16 + j] = g_z[(size_t)(b0c + g16 + j) * HH + t];

    const size_t pb = (size_t)p * 768;
    const u64 brc2 = pk2(bih[pb + t]       + bhh[pb + t]);
    const u64 bzc2 = pk2(bih[pb + 256 + t] + bhh[pb + 256 + t]);
    const u64 bin2 = pk2(bih[pb + 512 + t]);
    const u64 bhn2 = pk2(bhh[pb + 512 + t]);
    const float wl  = Wlin[(size_t)p * HH + t];
    const float blv = blin[p];
    // fused weights: [k][256] float4, this thread's column = +t
    const float4* __restrict__ Wf  =
        reinterpret_cast<const float4*>(g_Wf4)  + (size_t)p * HH * HH + t;
    const float4* __restrict__ Wif =
        reinterpret_cast<const float4*>(g_Wif4) + (size_t)p * KK * HH + t;

    __syncthreads();

    for (int l = 0; l < LL; l++) {
        // gather inputs for this step: seq[l=0] = zero pad row; else X[:, 9+l, conn]
        if (l > 0) {
            const int bb = tid >> 4, kk = tid & 15;
            if (tid < 512) {   // 512 threads == 32 b * 16 k
                xg2[kk*HST + bb] =
                    X[((size_t)(b0c + bb) * TT + (9 + l)) * PP + cidx[kk]];
            }
        }
        __syncthreads();

        u64 ar2[8], az2[8], gi2[8], gh2[8];
        #pragma unroll
        for (int q = 0; q < 8; q++) { ar2[q]=brc2; az2[q]=bzc2; gi2[q]=bin2; gh2[q]=bhn2; }

        // input contribution (K = 16): 1 LDG.128 per k
        #pragma unroll
        for (int k = 0; k < KK; k++) {
            const float4 w = Wif[(size_t)k * HH];
            const u64 wr = pk2(w.x);
            const u64 wz = pk2(w.y);
            const u64 wn = pk2(w.z);
            const ulonglong2* hp =
                reinterpret_cast<const ulonglong2*>(&xg2[k*HST + g16]);
            #pragma unroll
            for (int q = 0; q < 4; q++) {
                ulonglong2 hv = hp[q];
                ar2[2*q]   = ffma2(hv.x, wr, ar2[2*q]);
                az2[2*q]   = ffma2(hv.x, wz, az2[2*q]);
                gi2[2*q]   = ffma2(hv.x, wn, gi2[2*q]);
                ar2[2*q+1] = ffma2(hv.y, wr, ar2[2*q+1]);
                az2[2*q+1] = ffma2(hv.y, wz, az2[2*q+1]);
                gi2[2*q+1] = ffma2(hv.y, wn, gi2[2*q+1]);
            }
        }

        // hidden contribution (H = 256) — the hot loop: 1 LDG.128 per k
        #pragma unroll 1
        for (int kk = 0; kk < HH; kk += 4) {
            #pragma unroll
            for (int j = 0; j < 4; j++) {
                const int k = kk + j;
                const float4 w = Wf[(size_t)k * HH];
                const u64 wr = pk2(w.x);
                const u64 wz = pk2(w.y);
                const u64 wn = pk2(w.z);
                const ulonglong2* hp =
                    reinterpret_cast<const ulonglong2*>(&hs2[k*HST + g16]);
                #pragma unroll
                for (int q = 0; q < 4; q++) {
                    ulonglong2 hv = hp[q];
                    ar2[2*q]   = ffma2(hv.x, wr, ar2[2*q]);
                    az2[2*q]   = ffma2(hv.x, wz, az2[2*q]);
                    gh2[2*q]   = ffma2(hv.x, wn, gh2[2*q]);
                    ar2[2*q+1] = ffma2(hv.y, wr, ar2[2*q+1]);
                    az2[2*q+1] = ffma2(hv.y, wz, az2[2*q+1]);
                    gh2[2*q+1] = ffma2(hv.y, wn, gh2[2*q+1]);
                }
            }
        }

        // old h for the z-gate mix (read pre-barrier)
        float hold[16];
        #pragma unroll
        for (int j = 0; j < 4; j++) {
            float4 hv = *reinterpret_cast<const float4*>(&hs2[t*HST + g16 + 4*j]);
            hold[4*j]   = hv.x; hold[4*j+1] = hv.y;
            hold[4*j+2] = hv.z; hold[4*j+3] = hv.w;
        }

        float hnew[16];
        #pragma unroll
        for (int q = 0; q < 8; q++) {
            float a0,a1,z0,z1,i0,i1,n0,n1;
            upk2(ar2[q], a0, a1);
            upk2(az2[q], z0, z1);
            upk2(gi2[q], i0, i1);
            upk2(gh2[q], n0, n1);
            float r0 = fsig(a0), r1 = fsig(a1);
            float zz0 = fsig(z0), zz1 = fsig(z1);
            float nn0 = ftanh_(i0 + r0 * n0);
            float nn1 = ftanh_(i1 + r1 * n1);
            hnew[2*q]   = (1.0f - zz0) * nn0 + zz0 * hold[2*q];
            hnew[2*q+1] = (1.0f - zz1) * nn1 + zz1 * hold[2*q+1];
        }

        // pred partials from registers: warp-reduce per batch
        #pragma unroll
        for (int i = 0; i < 16; i++) {
            float v = fmaxf(hnew[i], 0.0f) * wl;
            v += __shfl_xor_sync(0xffffffffu, v, 16);
            v += __shfl_xor_sync(0xffffffffu, v, 8);
            v += __shfl_xor_sync(0xffffffffu, v, 4);
            v += __shfl_xor_sync(0xffffffffu, v, 2);
            v += __shfl_xor_sync(0xffffffffu, v, 1);
            if (lane == i) psum[g][wg][i] = v;
        }

        __syncthreads();   // all reads of old hs2/xg2 + psum writes complete

        // commit new hidden state (k-major)
        #pragma unroll
        for (int j = 0; j < 4; j++) {
            *reinterpret_cast<float4*>(&hs2[t*HST + g16 + 4*j]) =
                make_float4(hnew[4*j], hnew[4*j+1], hnew[4*j+2], hnew[4*j+3]);
        }
        // finalize pred for step l (psum visible post-barrier)
        if (tid < 32) {
            int gg = tid >> 4, bidx = tid & 15;
            float s = 0.0f;
            #pragma unroll
            for (int w = 0; w < 8; w++) s += psum[gg][w][bidx];
            pred[((size_t)(p*BB + b0c + gg*16 + bidx)) * LL + l] = s + blv;
        }
    }
}

extern "C" void kernel_launch(void* const* d_in, const int* in_sizes, int n_in,
                              void* d_out, int out_size)
{
    const float* X         = (const float*)d_in[0];
    const int*   conn_idx  = (const int*)  d_in[1];
    const float* W_ih_left = (const float*)d_in[2];
    const float* W_hh_left = (const float*)d_in[3];
    const float* b_ih_left = (const float*)d_in[4];
    const float* b_hh_left = (const float*)d_in[5];
    const float* W_ih_1    = (const float*)d_in[6];
    // d_in[7] = W_hh_1: unused (hidden state is 0 for gru_1's single step)
    const float* b_ih_1    = (const float*)d_in[8];
    const float* b_hh_1    = (const float*)d_in[9];
    const float* W_mu      = (const float*)d_in[10];
    const float* b_mu      = (const float*)d_in[11];
    const float* W_std     = (const float*)d_in[12];
    const float* b_std     = (const float*)d_in[13];
    const float* W_mean    = (const float*)d_in[14];
    const float* b_mean    = (const float*)d_in[15];
    const float* W_disp    = (const float*)d_in[16];
    const float* b_disp    = (const float*)d_in[17];
    const float* W_ih_nets = (const float*)d_in[18];
    const float* W_hh_nets = (const float*)d_in[19];
    const float* b_ih_nets = (const float*)d_in[20];
    const float* b_hh_nets = (const float*)d_in[21];
    const float* W_lin     = (const float*)d_in[22];
    const float* b_lin     = (const float*)d_in[23];
    const float* z_noise   = (const float*)d_in[24];

    float* out = (float*)d_out;
    float* pred       = out;
    float* out_logvar = out + 409600;
    float* out_mu     = out + 409600 + 16384;
    float* out_mean   = out + 409600 + 2*16384;
    float* out_disp   = out + 409600 + 2*16384 + 4096;

    float *wf4, *wif4, *wtenc;
    cudaGetSymbolAddress((void**)&wf4,   g_Wf4);
    cudaGetSymbolAddress((void**)&wif4,  g_Wif4);
    cudaGetSymbolAddress((void**)&wtenc, g_WTenc);

    dim3 tb(32, 8);

    repack_hh<<<dim3(1, HH, PP), HH>>>(W_hh_nets, wf4);                 // 0
    repack_ih<<<PP, HH>>>(W_ih_nets, wif4);                             // 1
    transpose_k<<<dim3(8, 24, 1), tb>>>(W_hh_left, wtenc + OFF_HHL, 768, 256); // 2

    EncT e;                                                             // 3
    e.in[0] = W_ih_left; e.out[0] = wtenc + OFF_IHL;  e.R[0] = 768; e.C[0] = 64;
    e.in[1] = W_ih_1;    e.out[1] = wtenc + OFF_IH1;  e.R[1] = 768; e.C[1] = 256;
    e.in[2] = W_mu;      e.out[2] = wtenc + OFF_MU;   e.R[2] = 256; e.C[2] = 256;
    e.in[3] = W_std;     e.out[3] = wtenc + OFF_STD;  e.R[3] = 256; e.C[3] = 256;
    e.in[4] = W_mean;    e.out[4] = wtenc + OFF_MEAN; e.R[4] = 64;  e.C[4] = 256;
    e.in[5] = W_disp;    e.out[5] = wtenc + OFF_DISP; e.R[5] = 64;  e.C[5] = 256;
    transpose_multi<<<dim3(8, 24, 6), tb>>>(e);

    encoder_kernel<<<BB, 256>>>(                                        // 4
        X, b_ih_left, b_hh_left, b_ih_1, b_hh_1,
        b_mu, b_std, b_mean, b_disp, z_noise,
        out_logvar, out_mu, out_mean, out_disp);

    nets_kernel<<<dim3(PP, BB/32), 512>>>(                              // 5
        X, conn_idx, b_ih_nets, b_hh_nets, W_lin, b_lin, pred);
}

// round 8
// speedup vs baseline: 1.9551x; 1.0595x over previous
#include <cuda_runtime.h>
#include <math.h>

// Problem dims
#define BB 64     // batch
#define TT 110    // timesteps
#define PP 64     // series
#define HH 256    // hidden
#define KK 16     // connections
#define LL 100    // nets seq length

typedef unsigned long long u64;

// Output layout (tuple concat, all f32):
//   pred   (P,B,L,1) : 409600  @ 0
//   logvar (B,H)     : 16384   @ 409600
//   mu     (B,H)     : 16384   @ 425984
//   mean   (B,P)     : 4096    @ 442368
//   disp   (B,P)     : 4096    @ 446464

__device__ float  g_z[BB * HH];                        // latent z scratch
__device__ float4 g_Wrz4[(size_t)PP * (HH/2) * HH];    // 32MB: {r0,z0,r1,z1} per (p, kpair, t)
__device__ float2 g_Wn2 [(size_t)PP * (HH/2) * HH];    // 16MB: {n0,n1}       per (p, kpair, t)
__device__ float4 g_Wirz4[(size_t)PP * (KK/2) * HH];   // 2MB
__device__ float2 g_Win2 [(size_t)PP * (KK/2) * HH];   // 1MB
__device__ float  g_WTenc[606208];                     // encoder weights transposed

#define OFF_HHL  0        // W_hh_left^T  [256][768]
#define OFF_IHL  196608   // W_ih_left^T  [64][768]
#define OFF_IH1  245760   // W_ih_1^T     [256][768]
#define OFF_MU   442368   // W_mu^T       [256][256]
#define OFF_STD  507904   // W_std^T      [256][256]
#define OFF_MEAN 573440   // W_mean^T     [256][64]
#define OFF_DISP 589824   // W_disp^T     [256][64]

__device__ __forceinline__ u64 pk2(float x) {
    u64 r; asm("mov.b64 %0, {%1, %1};" : "=l"(r) : "f"(x)); return r;
}
__device__ __forceinline__ u64 ffma2(u64 a, u64 b, u64 c) {
    u64 d; asm("fma.rn.f32x2 %0, %1, %2, %3;" : "=l"(d) : "l"(a), "l"(b), "l"(c)); return d;
}
__device__ __forceinline__ void upk2(u64 a, float& lo, float& hi) {
    asm("mov.b64 {%0, %1}, %2;" : "=f"(lo), "=f"(hi) : "l"(a));
}
__device__ __forceinline__ float fsig(float x) {
    return __fdividef(1.0f, 1.0f + __expf(-x));
}
__device__ __forceinline__ float ftanh_(float x) {
    float e = __expf(fminf(fmaxf(2.0f * x, -80.0f), 80.0f));
    return __fdividef(e - 1.0f, e + 1.0f);
}

// ------------------------------------------------------------------
// Repack Whh_nets (P,768,256) -> k-paired layout, via SMEM tiles so both
// sides stay coalesced. Block (32,8); grid (t-tiles=8, k-tiles=8, P).
//   Wrz4[p][kp][t] = {r(2kp,t), z(2kp,t), r(2kp+1,t), z(2kp+1,t)}
//   Wn2 [p][kp][t] = {n(2kp,t), n(2kp+1,t)}
// where r-row = t, z-row = 256+t, n-row = 512+t of the (768,256) matrix.
// ------------------------------------------------------------------
__global__ void repack_hh_pair(const float* __restrict__ in,
                               float4* __restrict__ outrz,
                               float2* __restrict__ outn)
{
    __shared__ float tr[32][33], tz[32][33], tn[32][33];
    const int p  = blockIdx.z;
    const int t0 = blockIdx.x * 32;
    const int k0 = blockIdx.y * 32;
    const int tx = threadIdx.x, ty = threadIdx.y;
    const float* W = in + (size_t)p * 768 * HH;

    #pragma unroll
    for (int r = ty; r < 32; r += 8) {
        tr[r][tx] = W[(size_t)(0*HH + t0 + r) * HH + k0 + tx];
        tz[r][tx] = W[(size_t)(1*HH + t0 + r) * HH + k0 + tx];
        tn[r][tx] = W[(size_t)(2*HH + t0 + r) * HH + k0 + tx];
    }
    __syncthreads();

    #pragma unroll
    for (int kp = ty; kp < 16; kp += 8) {
        const size_t o = ((size_t)p * (HH/2) + (k0 >> 1) + kp) * HH + t0 + tx;
        outrz[o] = make_float4(tr[tx][2*kp], tz[tx][2*kp],
                               tr[tx][2*kp+1], tz[tx][2*kp+1]);
        outn[o]  = make_float2(tn[tx][2*kp], tn[tx][2*kp+1]);
    }
}

// Repack Wih_nets (P,768,16) -> k-paired layout. Small (3MB): simple version.
// Block 256 (=t), grid P. Reads are strided but total volume is tiny.
__global__ void repack_ih_pair(const float* __restrict__ in,
                               float4* __restrict__ outrz,
                               float2* __restrict__ outn)
{
    const int p = blockIdx.x, t = threadIdx.x;
    const float* W = in + (size_t)p * 768 * KK;
    #pragma unroll
    for (int kp = 0; kp < KK/2; kp++) {
        const int k = 2*kp;
        const size_t o = ((size_t)p * (KK/2) + kp) * HH + t;
        outrz[o] = make_float4(W[(size_t)(0*HH + t) * KK + k],
                               W[(size_t)(1*HH + t) * KK + k],
                               W[(size_t)(0*HH + t) * KK + k + 1],
                               W[(size_t)(1*HH + t) * KK + k + 1]);
        outn[o]  = make_float2(W[(size_t)(2*HH + t) * KK + k],
                               W[(size_t)(2*HH + t) * KK + k + 1]);
    }
}

// ------------------------------------------------------------------
// Batched tiled transpose: in (Z, R, C) -> out (Z, C, R)
// ------------------------------------------------------------------
__global__ void transpose_k(const float* __restrict__ in, float* __restrict__ out,
                            int R, int C)
{
    __shared__ float tile[32][33];
    const size_t zoff = (size_t)blockIdx.z * R * C;
    in  += zoff;
    out += zoff;
    const int x = blockIdx.x * 32 + threadIdx.x;
    const int ybase = blockIdx.y * 32;
    #pragma unroll
    for (int j = threadIdx.y; j < 32; j += 8) {
        int y = ybase + j;
        if (x < C && y < R) tile[j][threadIdx.x] = in[(size_t)y * C + x];
    }
    __syncthreads();
    const int xo = ybase + threadIdx.x;
    const int yobase = blockIdx.x * 32;
    #pragma unroll
    for (int j = threadIdx.y; j < 32; j += 8) {
        int yo = yobase + j;
        if (yo < C && xo < R) out[(size_t)yo * R + xo] = tile[threadIdx.x][j];
    }
}

// Multi-matrix transpose: blockIdx.z selects one of 6 matrices
struct EncT {
    const float* in[6];
    float*       out[6];
    int          R[6];
    int          C[6];
};
__global__ void transpose_multi(EncT e)
{
    __shared__ float tile[32][33];
    const int m = blockIdx.z;
    const float* __restrict__ in = e.in[m];
    float* __restrict__ out = e.out[m];
    const int R = e.R[m], C = e.C[m];
    const int x = blockIdx.x * 32 + threadIdx.x;
    const int ybase = blockIdx.y * 32;
    #pragma unroll
    for (int j = threadIdx.y; j < 32; j += 8) {
        int y = ybase + j;
        if (x < C && y < R) tile[j][threadIdx.x] = in[(size_t)y * C + x];
    }
    __syncthreads();
    const int xo = ybase + threadIdx.x;
    const int yobase = blockIdx.x * 32;
    #pragma unroll
    for (int j = threadIdx.y; j < 32; j += 8) {
        int yo = yobase + j;
        if (yo < C && xo < R) out[(size_t)yo * R + xo] = tile[threadIdx.x][j];
    }
}

// ------------------------------------------------------------------
// Encoder: gru_left (10 steps) -> gru_1 (1 step, h0=0) -> heads + z
// ------------------------------------------------------------------
__global__ void __launch_bounds__(256) encoder_kernel(
    const float* __restrict__ X,
    const float* __restrict__ bih_l, const float* __restrict__ bhh_l,
    const float* __restrict__ bih1,  const float* __restrict__ bhh1,
    const float* __restrict__ bmu,   const float* __restrict__ bstd,
    const float* __restrict__ bmean, const float* __restrict__ bdisp,
    const float* __restrict__ z_noise,
    float* __restrict__ out_logvar, float* __restrict__ out_mu,
    float* __restrict__ out_mean,   float* __restrict__ out_disp)
{
    const int b = blockIdx.x;
    const int t = threadIdx.x;
    __shared__ float hs[HH];
    __shared__ float xs[PP];
    hs[t] = 0.0f;

    const float bir = bih_l[t]        + bhh_l[t];
    const float biz = bih_l[HH + t]   + bhh_l[HH + t];
    const float bin = bih_l[2*HH + t];
    const float bhn = bhh_l[2*HH + t];
    const float* __restrict__ Wh = g_WTenc + OFF_HHL;
    const float* __restrict__ Wi = g_WTenc + OFF_IHL;
    __syncthreads();

    for (int s = 0; s < 10; s++) {
        if (t < PP) xs[t] = X[((size_t)b * TT + s) * PP + t];
        __syncthreads();
        float ar = bir, az = biz, an = bin, gn = bhn;
        #pragma unroll 4
        for (int k = 0; k < HH; k++) {
            float hk = hs[k];
            ar += hk * Wh[k*768 + t];
            az += hk * Wh[k*768 + 256 + t];
            gn += hk * Wh[k*768 + 512 + t];
        }
        #pragma unroll 4
        for (int k = 0; k < PP; k++) {
            float xk = xs[k];
            ar += xk * Wi[k*768 + t];
            az += xk * Wi[k*768 + 256 + t];
            an += xk * Wi[k*768 + 512 + t];
        }
        float r  = fsig(ar);
        float zz = fsig(az);
        float n  = ftanh_(an + r * gn);
        float hnew = (1.0f - zz) * n + zz * hs[t];
        __syncthreads();
        hs[t] = hnew;
        __syncthreads();
    }

    {
        const float* __restrict__ W1 = g_WTenc + OFF_IH1;
        float ar = bih1[t]        + bhh1[t];
        float az = bih1[HH + t]   + bhh1[HH + t];
        float an = bih1[2*HH + t];
        float gn = bhh1[2*HH + t];
        #pragma unroll 4
        for (int k = 0; k < HH; k++) {
            float hk = hs[k];
            ar += hk * W1[k*768 + t];
            az += hk * W1[k*768 + 256 + t];
            an += hk * W1[k*768 + 512 + t];
        }
        float r  = fsig(ar);
        float zz = fsig(az);
        float n  = ftanh_(an + r * gn);
        float h1 = (1.0f - zz) * n;
        __syncthreads();
        hs[t] = h1;
        __syncthreads();
    }

    {
        float mu = bmu[t], lv = bstd[t];
        const float* __restrict__ Wm = g_WTenc + OFF_MU;
        const float* __restrict__ Ws = g_WTenc + OFF_STD;
        #pragma unroll 4
        for (int k = 0; k < HH; k++) {
            float hk = hs[k];
            mu += hk * Wm[k*256 + t];
            lv += hk * Ws[k*256 + t];
        }
        out_mu[b*HH + t]     = mu;
        out_logvar[b*HH + t] = lv;
        g_z[b*HH + t] = mu + expf(0.5f * lv) * z_noise[b*HH + t];

        if (t < PP) {
            float m = bmean[t], d = bdisp[t];
            const float* __restrict__ Wme = g_WTenc + OFF_MEAN;
            const float* __restrict__ Wd  = g_WTenc + OFF_DISP;
            #pragma unroll 4
            for (int k = 0; k < HH; k++) {
                float hk = hs[k];
                m += hk * Wme[k*64 + t];
                d += hk * Wd[k*64 + t];
            }
            m = expf(m);
            m = fminf(fmaxf(m, 1e-5f), 1e6f);
            d = log1pf(expf(d));
            d = fminf(fmaxf(d, 1e-4f), 1e4f);
            out_mean[b*PP + t] = m;
            out_disp[b*PP + t] = d;
        }
    }
}

// ------------------------------------------------------------------
// Per-series GRU nets: grid (64, 2), 512 threads, R4 structure.
// Thread = 1 hidden unit x 16 batches (32 u64 accums).
// k-paired weights: per 2 k-steps ONE LDG.128 {r0,z0,r1,z1} + ONE
// LDG.64 {n0,n1} — same bytes as R4 (24B/thread/2k), 1/3 the LDG slots.
// h stored k-major (hs2[k][32b], stride 36) -> LDS.128 = two f32x2
// operands. Two barriers per step (known-good R4 schedule).
// ------------------------------------------------------------------
#define BT 16
#define HST 36                 // hs row stride (32 batches + 4 pad)

__global__ void __launch_bounds__(512, 1) nets_kernel(
    const float* __restrict__ X,
    const int*   __restrict__ conn_idx,
    const float* __restrict__ bih,   // (P, 768)
    const float* __restrict__ bhh,   // (P, 768)
    const float* __restrict__ Wlin,  // (P, 1, 256)
    const float* __restrict__ blin,  // (P, 1)
    float* __restrict__ pred)        // (P, B, L, 1)
{
    const int p    = blockIdx.x;
    const int b0c  = blockIdx.y * 32;
    const int tid  = threadIdx.x;
    const int g    = tid >> 8;        // batch-group 0/1 (16 batches each)
    const int t    = tid & 255;       // hidden unit
    const int g16  = g << 4;
    const int lane = tid & 31;
    const int wg   = (tid >> 5) & 7;  // warp within group

    __shared__ __align__(16) float hs2[HH * HST];   // [k][32b]
    __shared__ __align__(16) float xg2[KK * HST];   // [k][32b]
    __shared__ float psum[2][8][16];
    __shared__ int   cidx[KK];

    if (tid < KK) cidx[tid] = conn_idx[p*KK + tid];
    for (int i = tid; i < KK*HST; i += 512) xg2[i] = 0.0f;
    #pragma unroll
    for (int j = 0; j < BT; j++)
        hs2[t*HST + g16 + j] = g_z[(size_t)(b0c + g16 + j) * HH + t];

    const size_t pb = (size_t)p * 768;
    const u64 brc2 = pk2(bih[pb + t]       + bhh[pb + t]);
    const u64 bzc2 = pk2(bih[pb + 256 + t] + bhh[pb + 256 + t]);
    const u64 bin2 = pk2(bih[pb + 512 + t]);
    const u64 bhn2 = pk2(bhh[pb + 512 + t]);
    const float wl  = Wlin[(size_t)p * HH + t];
    const float blv = blin[p];
    // k-paired weights: element [kp*HH], this thread's column = +t
    const float4* __restrict__ Wrz = g_Wrz4  + (size_t)p * (HH/2) * HH + t;
    const float2* __restrict__ Wn  = g_Wn2   + (size_t)p * (HH/2) * HH + t;
    const float4* __restrict__ Wirz= g_Wirz4 + (size_t)p * (KK/2) * HH + t;
    const float2* __restrict__ Win = g_Win2  + (size_t)p * (KK/2) * HH + t;

    __syncthreads();

    for (int l = 0; l < LL; l++) {
        // gather inputs for this step: seq[l=0] = zero pad row; else X[:, 9+l, conn]
        if (l > 0) {
            const int bb = tid >> 4, kk = tid & 15;
            xg2[kk*HST + bb] =
                X[((size_t)(b0c + bb) * TT + (9 + l)) * PP + cidx[kk]];
        }
        __syncthreads();

        u64 ar2[8], az2[8], gi2[8], gh2[8];
        #pragma unroll
        for (int q = 0; q < 8; q++) { ar2[q]=brc2; az2[q]=bzc2; gi2[q]=bin2; gh2[q]=bhn2; }

        // input contribution (K = 16): 8 k-pairs
        #pragma unroll
        for (int kp = 0; kp < KK/2; kp++) {
            const float4 w4 = Wirz[(size_t)kp * HH];
            const float2 w2 = Win [(size_t)kp * HH];
            const u64 wr0 = pk2(w4.x), wz0 = pk2(w4.y), wn0 = pk2(w2.x);
            const u64 wr1 = pk2(w4.z), wz1 = pk2(w4.w), wn1 = pk2(w2.y);
            const ulonglong2* h0 =
                reinterpret_cast<const ulonglong2*>(&xg2[(2*kp)*HST + g16]);
            const ulonglong2* h1 =
                reinterpret_cast<const ulonglong2*>(&xg2[(2*kp+1)*HST + g16]);
            #pragma unroll
            for (int q = 0; q < 4; q++) {
                ulonglong2 a = h0[q];
                ar2[2*q]   = ffma2(a.x, wr0, ar2[2*q]);
                az2[2*q]   = ffma2(a.x, wz0, az2[2*q]);
                gi2[2*q]   = ffma2(a.x, wn0, gi2[2*q]);
                ar2[2*q+1] = ffma2(a.y, wr0, ar2[2*q+1]);
                az2[2*q+1] = ffma2(a.y, wz0, az2[2*q+1]);
                gi2[2*q+1] = ffma2(a.y, wn0, gi2[2*q+1]);
            }
            #pragma unroll
            for (int q = 0; q < 4; q++) {
                ulonglong2 a = h1[q];
                ar2[2*q]   = ffma2(a.x, wr1, ar2[2*q]);
                az2[2*q]   = ffma2(a.x, wz1, az2[2*q]);
                gi2[2*q]   = ffma2(a.x, wn1, gi2[2*q]);
                ar2[2*q+1] = ffma2(a.y, wr1, ar2[2*q+1]);
                az2[2*q+1] = ffma2(a.y, wz1, az2[2*q+1]);
                gi2[2*q+1] = ffma2(a.y, wn1, gi2[2*q+1]);
            }
        }

        // hidden contribution (H = 256): 128 k-pairs — the hot loop
        #pragma unroll 1
        for (int kpp = 0; kpp < HH/2; kpp += 2) {
            #pragma unroll
            for (int j = 0; j < 2; j++) {
                const int kp = kpp + j;
                const float4 w4 = Wrz[(size_t)kp * HH];
                const float2 w2 = Wn [(size_t)kp * HH];
                const u64 wr0 = pk2(w4.x), wz0 = pk2(w4.y), wn0 = pk2(w2.x);
                const u64 wr1 = pk2(w4.z), wz1 = pk2(w4.w), wn1 = pk2(w2.y);
                const ulonglong2* h0 =
                    reinterpret_cast<const ulonglong2*>(&hs2[(2*kp)*HST + g16]);
                const ulonglong2* h1 =
                    reinterpret_cast<const ulonglong2*>(&hs2[(2*kp+1)*HST + g16]);
                #pragma unroll
                for (int q = 0; q < 4; q++) {
                    ulonglong2 a = h0[q];
                    ar2[2*q]   = ffma2(a.x, wr0, ar2[2*q]);
                    az2[2*q]   = ffma2(a.x, wz0, az2[2*q]);
                    gh2[2*q]   = ffma2(a.x, wn0, gh2[2*q]);
                    ar2[2*q+1] = ffma2(a.y, wr0, ar2[2*q+1]);
                    az2[2*q+1] = ffma2(a.y, wz0, az2[2*q+1]);
                    gh2[2*q+1] = ffma2(a.y, wn0, gh2[2*q+1]);
                }
                #pragma unroll
                for (int q = 0; q < 4; q++) {
                    ulonglong2 a = h1[q];
                    ar2[2*q]   = ffma2(a.x, wr1, ar2[2*q]);
                    az2[2*q]   = ffma2(a.x, wz1, az2[2*q]);
                    gh2[2*q]   = ffma2(a.x, wn1, gh2[2*q]);
                    ar2[2*q+1] = ffma2(a.y, wr1, ar2[2*q+1]);
                    az2[2*q+1] = ffma2(a.y, wz1, az2[2*q+1]);
                    gh2[2*q+1] = ffma2(a.y, wn1, gh2[2*q+1]);
                }
            }
        }

        // old h for the z-gate mix (read pre-barrier)
        float hold[16];
        #pragma unroll
        for (int j = 0; j < 4; j++) {
            float4 hv = *reinterpret_cast<const float4*>(&hs2[t*HST + g16 + 4*j]);
            hold[4*j]   = hv.x; hold[4*j+1] = hv.y;
            hold[4*j+2] = hv.z; hold[4*j+3] = hv.w;
        }

        float hnew[16];
        #pragma unroll
        for (int q = 0; q < 8; q++) {
            float a0,a1,z0,z1,i0,i1,n0,n1;
            upk2(ar2[q], a0, a1);
            upk2(az2[q], z0, z1);
            upk2(gi2[q], i0, i1);
            upk2(gh2[q], n0, n1);
            float r0 = fsig(a0), r1 = fsig(a1);
            float zz0 = fsig(z0), zz1 = fsig(z1);
            float nn0 = ftanh_(i0 + r0 * n0);
            float nn1 = ftanh_(i1 + r1 * n1);
            hnew[2*q]   = (1.0f - zz0) * nn0 + zz0 * hold[2*q];
            hnew[2*q+1] = (1.0f - zz1) * nn1 + zz1 * hold[2*q+1];
        }

        // pred partials from registers: warp-reduce per batch
        #pragma unroll
        for (int i = 0; i < 16; i++) {
            float v = fmaxf(hnew[i], 0.0f) * wl;
            v += __shfl_xor_sync(0xffffffffu, v, 16);
            v += __shfl_xor_sync(0xffffffffu, v, 8);
            v += __shfl_xor_sync(0xffffffffu, v, 4);
            v += __shfl_xor_sync(0xffffffffu, v, 2);
            v += __shfl_xor_sync(0xffffffffu, v, 1);
            if (lane == i) psum[g][wg][i] = v;
        }

        __syncthreads();   // all reads of old hs2/xg2 + psum writes complete

        // commit new hidden state (k-major)
        #pragma unroll
        for (int j = 0; j < 4; j++) {
            *reinterpret_cast<float4*>(&hs2[t*HST + g16 + 4*j]) =
                make_float4(hnew[4*j], hnew[4*j+1], hnew[4*j+2], hnew[4*j+3]);
        }
        // finalize pred for step l (psum visible post-barrier)
        if (tid < 32) {
            int gg = tid >> 4, bidx = tid & 15;
            float s = 0.0f;
            #pragma unroll
            for (int w = 0; w < 8; w++) s += psum[gg][w][bidx];
            pred[((size_t)(p*BB + b0c + gg*16 + bidx)) * LL + l] = s + blv;
        }
    }
}

extern "C" void kernel_launch(void* const* d_in, const int* in_sizes, int n_in,
                              void* d_out, int out_size)
{
    const float* X         = (const float*)d_in[0];
    const int*   conn_idx  = (const int*)  d_in[1];
    const float* W_ih_left = (const float*)d_in[2];
    const float* W_hh_left = (const float*)d_in[3];
    const float* b_ih_left = (const float*)d_in[4];
    const float* b_hh_left = (const float*)d_in[5];
    const float* W_ih_1    = (const float*)d_in[6];
    // d_in[7] = W_hh_1: unused (hidden state is 0 for gru_1's single step)
    const float* b_ih_1    = (const float*)d_in[8];
    const float* b_hh_1    = (const float*)d_in[9];
    const float* W_mu      = (const float*)d_in[10];
    const float* b_mu      = (const float*)d_in[11];
    const float* W_std     = (const float*)d_in[12];
    const float* b_std     = (const float*)d_in[13];
    const float* W_mean    = (const float*)d_in[14];
    const float* b_mean    = (const float*)d_in[15];
    const float* W_disp    = (const float*)d_in[16];
    const float* b_disp    = (const float*)d_in[17];
    const float* W_ih_nets = (const float*)d_in[18];
    const float* W_hh_nets = (const float*)d_in[19];
    const float* b_ih_nets = (const float*)d_in[20];
    const float* b_hh_nets = (const float*)d_in[21];
    const float* W_lin     = (const float*)d_in[22];
    const float* b_lin     = (const float*)d_in[23];
    const float* z_noise   = (const float*)d_in[24];

    float* out = (float*)d_out;
    float* pred       = out;
    float* out_logvar = out + 409600;
    float* out_mu     = out + 409600 + 16384;
    float* out_mean   = out + 409600 + 2*16384;
    float* out_disp   = out + 409600 + 2*16384 + 4096;

    float4 *wrz, *wirz;
    float2 *wn, *win;
    float  *wtenc;
    cudaGetSymbolAddress((void**)&wrz,   g_Wrz4);
    cudaGetSymbolAddress((void**)&wn,    g_Wn2);
    cudaGetSymbolAddress((void**)&wirz,  g_Wirz4);
    cudaGetSymbolAddress((void**)&win,   g_Win2);
    cudaGetSymbolAddress((void**)&wtenc, g_WTenc);

    dim3 tb(32, 8);

    repack_hh_pair<<<dim3(8, 8, PP), tb>>>(W_hh_nets, wrz, wn);         // 0
    repack_ih_pair<<<PP, 256>>>(W_ih_nets, wirz, win);                  // 1
    transpose_k<<<dim3(8, 24, 1), tb>>>(W_hh_left, wtenc + OFF_HHL, 768, 256); // 2

    EncT e;                                                             // 3
    e.in[0] = W_ih_left; e.out[0] = wtenc + OFF_IHL;  e.R[0] = 768; e.C[0] = 64;
    e.in[1] = W_ih_1;    e.out[1] = wtenc + OFF_IH1;  e.R[1] = 768; e.C[1] = 256;
    e.in[2] = W_mu;      e.out[2] = wtenc + OFF_MU;   e.R[2] = 256; e.C[2] = 256;
    e.in[3] = W_std;     e.out[3] = wtenc + OFF_STD;  e.R[3] = 256; e.C[3] = 256;
    e.in[4] = W_mean;    e.out[4] = wtenc + OFF_MEAN; e.R[4] = 64;  e.C[4] = 256;
    e.in[5] = W_disp;    e.out[5] = wtenc + OFF_DISP; e.R[5] = 64;  e.C[5] = 256;
    transpose_multi<<<dim3(8, 24, 6), tb>>>(e);

    encoder_kernel<<<BB, 256>>>(                                        // 4
        X, b_ih_left, b_hh_left, b_ih_1, b_hh_1,
        b_mu, b_std, b_mean, b_disp, z_noise,
        out_logvar, out_mu, out_mean, out_disp);

    nets_kernel<<<dim3(PP, BB/32), 512>>>(                              // 5
        X, conn_idx, b_ih_nets, b_hh_nets, W_lin, b_lin, pred);
}

// round 9
// speedup vs baseline: 2.2056x; 1.1281x over previous
#include <cuda_runtime.h>
#include <math.h>

// Problem dims
#define BB 64     // batch
#define TT 110    // timesteps
#define PP 64     // series
#define HH 256    // hidden
#define KK 16     // connections
#define LL 100    // nets seq length

typedef unsigned long long u64;

// Output layout (tuple concat, all f32):
//   pred   (P,B,L,1) : 409600  @ 0
//   logvar (B,H)     : 16384   @ 409600
//   mu     (B,H)     : 16384   @ 425984
//   mean   (B,P)     : 4096    @ 442368
//   disp   (B,P)     : 4096    @ 446464

__device__ float g_z[BB * HH];                       // latent z scratch
__device__ float g_WThh[(size_t)PP * HH * 768];      // 48MB: Whh_nets transposed [p][k][768]
__device__ float g_WTih[(size_t)PP * KK * 768];      // 3MB:  Wih_nets transposed [p][k][768]
__device__ float g_WTenc[606208];                    // encoder weights transposed

#define OFF_HHL  0        // W_hh_left^T  [256][768]
#define OFF_IHL  196608   // W_ih_left^T  [64][768]
#define OFF_IH1  245760   // W_ih_1^T     [256][768]
#define OFF_MU   442368   // W_mu^T       [256][256]
#define OFF_STD  507904   // W_std^T      [256][256]
#define OFF_MEAN 573440   // W_mean^T     [256][64]
#define OFF_DISP 589824   // W_disp^T     [256][64]

__device__ __forceinline__ u64 pk2(float x) {
    u64 r; asm("mov.b64 %0, {%1, %1};" : "=l"(r) : "f"(x)); return r;
}
__device__ __forceinline__ u64 ffma2(u64 a, u64 b, u64 c) {
    u64 d; asm("fma.rn.f32x2 %0, %1, %2, %3;" : "=l"(d) : "l"(a), "l"(b), "l"(c)); return d;
}
__device__ __forceinline__ void upk2(u64 a, float& lo, float& hi) {
    asm("mov.b64 {%0, %1}, %2;" : "=f"(lo), "=f"(hi) : "l"(a));
}
__device__ __forceinline__ float fsig(float x) {
    return __fdividef(1.0f, 1.0f + __expf(-x));
}
__device__ __forceinline__ float ftanh_(float x) {
    float e = __expf(fminf(fmaxf(2.0f * x, -80.0f), 80.0f));
    return __fdividef(e - 1.0f, e + 1.0f);
}

// ------------------------------------------------------------------
// Launch 0: fused transpose of all 7 encoder matrices (blockIdx.z = m)
// ------------------------------------------------------------------
struct EncT7 {
    const float* in[7];
    float*       out[7];
    int          R[7];
    int          C[7];
};
__global__ void transpose_multi7(EncT7 e)
{
    __shared__ float tile[32][33];
    const int m = blockIdx.z;
    const float* __restrict__ in = e.in[m];
    float* __restrict__ out = e.out[m];
    const int R = e.R[m], C = e.C[m];
    const int x = blockIdx.x * 32 + threadIdx.x;
    const int ybase = blockIdx.y * 32;
    #pragma unroll
    for (int j = threadIdx.y; j < 32; j += 8) {
        int y = ybase + j;
        if (x < C && y < R) tile[j][threadIdx.x] = in[(size_t)y * C + x];
    }
    __syncthreads();
    const int xo = ybase + threadIdx.x;
    const int yobase = blockIdx.x * 32;
    #pragma unroll
    for (int j = threadIdx.y; j < 32; j += 8) {
        int yo = yobase + j;
        if (yo < C && xo < R) out[(size_t)yo * R + xo] = tile[threadIdx.x][j];
    }
}

// ------------------------------------------------------------------
// Launch 2: fused transpose of nets weights.
// z in [0,64):   Whh_nets p=z   (768,256) -> [p][256][768]
// z in [64,128): Wih_nets p=z-64 (768,16) -> [p][16][768]
// ------------------------------------------------------------------
__global__ void transpose_nets(const float* __restrict__ Whh,
                               const float* __restrict__ Wih,
                               float* __restrict__ outhh,
                               float* __restrict__ outih)
{
    __shared__ float tile[32][33];
    const int z = blockIdx.z;
    const float* __restrict__ in;
    float* __restrict__ out;
    int C;
    if (z < PP) {
        in  = Whh   + (size_t)z * 768 * HH;
        out = outhh + (size_t)z * HH * 768;
        C = HH;
    } else {
        in  = Wih   + (size_t)(z - PP) * 768 * KK;
        out = outih + (size_t)(z - PP) * KK * 768;
        C = KK;
    }
    const int R = 768;
    const int x = blockIdx.x * 32 + threadIdx.x;
    const int ybase = blockIdx.y * 32;
    #pragma unroll
    for (int j = threadIdx.y; j < 32; j += 8) {
        int y = ybase + j;
        if (x < C && y < R) tile[j][threadIdx.x] = in[(size_t)y * C + x];
    }
    __syncthreads();
    const int xo = ybase + threadIdx.x;
    const int yobase = blockIdx.x * 32;
    #pragma unroll
    for (int j = threadIdx.y; j < 32; j += 8) {
        int yo = yobase + j;
        if (yo < C && xo < R) out[(size_t)yo * R + xo] = tile[threadIdx.x][j];
    }
}

// ------------------------------------------------------------------
// Launch 1: Encoder: gru_left (10 steps) -> gru_1 (1 step) -> heads + z
// ------------------------------------------------------------------
__global__ void __launch_bounds__(256) encoder_kernel(
    const float* __restrict__ X,
    const float* __restrict__ bih_l, const float* __restrict__ bhh_l,
    const float* __restrict__ bih1,  const float* __restrict__ bhh1,
    const float* __restrict__ bmu,   const float* __restrict__ bstd,
    const float* __restrict__ bmean, const float* __restrict__ bdisp,
    const float* __restrict__ z_noise,
    float* __restrict__ out_logvar, float* __restrict__ out_mu,
    float* __restrict__ out_mean,   float* __restrict__ out_disp)
{
    const int b = blockIdx.x;
    const int t = threadIdx.x;
    __shared__ float hs[HH];
    __shared__ float xs[PP];
    hs[t] = 0.0f;

    const float bir = bih_l[t]        + bhh_l[t];
    const float biz = bih_l[HH + t]   + bhh_l[HH + t];
    const float bin = bih_l[2*HH + t];
    const float bhn = bhh_l[2*HH + t];
    const float* __restrict__ Wh = g_WTenc + OFF_HHL;
    const float* __restrict__ Wi = g_WTenc + OFF_IHL;
    __syncthreads();

    for (int s = 0; s < 10; s++) {
        if (t < PP) xs[t] = X[((size_t)b * TT + s) * PP + t];
        __syncthreads();
        float ar = bir, az = biz, an = bin, gn = bhn;
        #pragma unroll 4
        for (int k = 0; k < HH; k++) {
            float hk = hs[k];
            ar += hk * Wh[k*768 + t];
            az += hk * Wh[k*768 + 256 + t];
            gn += hk * Wh[k*768 + 512 + t];
        }
        #pragma unroll 4
        for (int k = 0; k < PP; k++) {
            float xk = xs[k];
            ar += xk * Wi[k*768 + t];
            az += xk * Wi[k*768 + 256 + t];
            an += xk * Wi[k*768 + 512 + t];
        }
        float r  = fsig(ar);
        float zz = fsig(az);
        float n  = ftanh_(an + r * gn);
        float hnew = (1.0f - zz) * n + zz * hs[t];
        __syncthreads();
        hs[t] = hnew;
        __syncthreads();
    }

    {
        const float* __restrict__ W1 = g_WTenc + OFF_IH1;
        float ar = bih1[t]        + bhh1[t];
        float az = bih1[HH + t]   + bhh1[HH + t];
        float an = bih1[2*HH + t];
        float gn = bhh1[2*HH + t];
        #pragma unroll 4
        for (int k = 0; k < HH; k++) {
            float hk = hs[k];
            ar += hk * W1[k*768 + t];
            az += hk * W1[k*768 + 256 + t];
            an += hk * W1[k*768 + 512 + t];
        }
        float r  = fsig(ar);
        float zz = fsig(az);
        float n  = ftanh_(an + r * gn);
        float h1 = (1.0f - zz) * n;
        __syncthreads();
        hs[t] = h1;
        __syncthreads();
    }

    {
        float mu = bmu[t], lv = bstd[t];
        const float* __restrict__ Wm = g_WTenc + OFF_MU;
        const float* __restrict__ Ws = g_WTenc + OFF_STD;
        #pragma unroll 4
        for (int k = 0; k < HH; k++) {
            float hk = hs[k];
            mu += hk * Wm[k*256 + t];
            lv += hk * Ws[k*256 + t];
        }
        out_mu[b*HH + t]     = mu;
        out_logvar[b*HH + t] = lv;
        g_z[b*HH + t] = mu + expf(0.5f * lv) * z_noise[b*HH + t];

        if (t < PP) {
            float m = bmean[t], d = bdisp[t];
            const float* __restrict__ Wme = g_WTenc + OFF_MEAN;
            const float* __restrict__ Wd  = g_WTenc + OFF_DISP;
            #pragma unroll 4
            for (int k = 0; k < HH; k++) {
                float hk = hs[k];
                m += hk * Wme[k*64 + t];
                d += hk * Wd[k*64 + t];
            }
            m = expf(m);
            m = fminf(fmaxf(m, 1e-5f), 1e6f);
            d = log1pf(expf(d));
            d = fminf(fmaxf(d, 1e-4f), 1e4f);
            out_mean[b*PP + t] = m;
            out_disp[b*PP + t] = d;
        }
    }
}

// ------------------------------------------------------------------
// Launch 3: Per-series GRU nets — EXACT best-known (4424us) config.
// grid (64, 2), 512 threads = 2 groups x 256 units, 1 CTA/SM.
// Thread = 1 hidden unit x 16 batches; f32x2 packed accumulators.
// h stored k-major (hs2[k][32b], stride 36) -> LDS.128 = two f32x2
// operands. Weights [p][k][768], 3x coalesced LDG.32 per k.
// ------------------------------------------------------------------
#define BT 16
#define HST 36                 // hs row stride (32 batches + 4 pad)

__global__ void __launch_bounds__(512, 1) nets_kernel(
    const float* __restrict__ X,
    const int*   __restrict__ conn_idx,
    const float* __restrict__ bih,   // (P, 768)
    const float* __restrict__ bhh,   // (P, 768)
    const float* __restrict__ Wlin,  // (P, 1, 256)
    const float* __restrict__ blin,  // (P, 1)
    float* __restrict__ pred)        // (P, B, L, 1)
{
    const int p    = blockIdx.x;
    const int b0c  = blockIdx.y * 32;
    const int tid  = threadIdx.x;
    const int g    = tid >> 8;        // batch-group 0/1 (16 batches each)
    const int t    = tid & 255;       // hidden unit
    const int g16  = g << 4;
    const int lane = tid & 31;
    const int wg   = (tid >> 5) & 7;  // warp within group

    __shared__ __align__(16) float hs2[HH * HST];   // [k][32b]
    __shared__ __align__(16) float xg2[KK * HST];   // [k][32b]
    __shared__ float psum[2][8][16];
    __shared__ int   cidx[KK];

    if (tid < KK) cidx[tid] = conn_idx[p*KK + tid];
    for (int i = tid; i < KK*HST; i += 512) xg2[i] = 0.0f;  // step 0 = zero row
    #pragma unroll
    for (int j = 0; j < BT; j++)
        hs2[t*HST + g16 + j] = g_z[(size_t)(b0c + g16 + j) * HH + t];

    const size_t pb = (size_t)p * 768;
    const u64 brc2 = pk2(bih[pb + t]       + bhh[pb + t]);
    const u64 bzc2 = pk2(bih[pb + 256 + t] + bhh[pb + 256 + t]);
    const u64 bin2 = pk2(bih[pb + 512 + t]);
    const u64 bhn2 = pk2(bhh[pb + 512 + t]);
    const float wl  = Wlin[(size_t)p * HH + t];
    const float blv = blin[p];
    const float* __restrict__ Whp = g_WThh + (size_t)p * HH * 768 + t;  // [k][768]
    const float* __restrict__ Wip = g_WTih + (size_t)p * KK * 768 + t;  // [k][768]

    __syncthreads();

    for (int l = 0; l < LL; l++) {
        u64 ar2[8], az2[8], gi2[8], gh2[8];
        #pragma unroll
        for (int q = 0; q < 8; q++) { ar2[q]=brc2; az2[q]=bzc2; gi2[q]=bin2; gh2[q]=bhn2; }

        // input contribution (K = 16)
        #pragma unroll
        for (int k = 0; k < KK; k++) {
            const float* r_ = Wip + (size_t)k * 768;
            const u64 wr = pk2(r_[0]);
            const u64 wz = pk2(r_[256]);
            const u64 wn = pk2(r_[512]);
            const ulonglong2* hp =
                reinterpret_cast<const ulonglong2*>(&xg2[k*HST + g16]);
            #pragma unroll
            for (int q = 0; q < 4; q++) {
                ulonglong2 hv = hp[q];
                ar2[2*q]   = ffma2(hv.x, wr, ar2[2*q]);
                az2[2*q]   = ffma2(hv.x, wz, az2[2*q]);
                gi2[2*q]   = ffma2(hv.x, wn, gi2[2*q]);
                ar2[2*q+1] = ffma2(hv.y, wr, ar2[2*q+1]);
                az2[2*q+1] = ffma2(hv.y, wz, az2[2*q+1]);
                gi2[2*q+1] = ffma2(hv.y, wn, gi2[2*q+1]);
            }
        }

        // hidden contribution (H = 256) — the hot loop
        #pragma unroll 1
        for (int kk = 0; kk < HH; kk += 4) {
            #pragma unroll
            for (int j = 0; j < 4; j++) {
                const int k = kk + j;
                const float* r_ = Whp + (size_t)k * 768;
                const u64 wr = pk2(r_[0]);
                const u64 wz = pk2(r_[256]);
                const u64 wn = pk2(r_[512]);
                const ulonglong2* hp =
                    reinterpret_cast<const ulonglong2*>(&hs2[k*HST + g16]);
                #pragma unroll
                for (int q = 0; q < 4; q++) {
                    ulonglong2 hv = hp[q];
                    ar2[2*q]   = ffma2(hv.x, wr, ar2[2*q]);
                    az2[2*q]   = ffma2(hv.x, wz, az2[2*q]);
                    gh2[2*q]   = ffma2(hv.x, wn, gh2[2*q]);
                    ar2[2*q+1] = ffma2(hv.y, wr, ar2[2*q+1]);
                    az2[2*q+1] = ffma2(hv.y, wz, az2[2*q+1]);
                    gh2[2*q+1] = ffma2(hv.y, wn, gh2[2*q+1]);
                }
            }
        }

        // old h for the z-gate mix (read pre-barrier)
        float hold[16];
        #pragma unroll
        for (int j = 0; j < 4; j++) {
            float4 hv = *reinterpret_cast<const float4*>(&hs2[t*HST + g16 + 4*j]);
            hold[4*j]   = hv.x; hold[4*j+1] = hv.y;
            hold[4*j+2] = hv.z; hold[4*j+3] = hv.w;
        }

        float hnew[16];
        #pragma unroll
        for (int q = 0; q < 8; q++) {
            float a0,a1,z0,z1,i0,i1,n0,n1;
            upk2(ar2[q], a0, a1);
            upk2(az2[q], z0, z1);
            upk2(gi2[q], i0, i1);
            upk2(gh2[q], n0, n1);
            float r0 = fsig(a0), r1 = fsig(a1);
            float zz0 = fsig(z0), zz1 = fsig(z1);
            float nn0 = ftanh_(i0 + r0 * n0);
            float nn1 = ftanh_(i1 + r1 * n1);
            hnew[2*q]   = (1.0f - zz0) * nn0 + zz0 * hold[2*q];
            hnew[2*q+1] = (1.0f - zz1) * nn1 + zz1 * hold[2*q+1];
        }

        // pred partials from registers: warp-reduce per batch
        #pragma unroll
        for (int i = 0; i < 16; i++) {
            float v = fmaxf(hnew[i], 0.0f) * wl;
            v += __shfl_xor_sync(0xffffffffu, v, 16);
            v += __shfl_xor_sync(0xffffffffu, v, 8);
            v += __shfl_xor_sync(0xffffffffu, v, 4);
            v += __shfl_xor_sync(0xffffffffu, v, 2);
            v += __shfl_xor_sync(0xffffffffu, v, 1);
            if (lane == i) psum[g][wg][i] = v;
        }

        __syncthreads();   // all reads of old hs2/xg2 + psum writes complete

        // commit new hidden state (k-major)
        #pragma unroll
        for (int j = 0; j < 4; j++) {
            *reinterpret_cast<float4*>(&hs2[t*HST + g16 + 4*j]) =
                make_float4(hnew[4*j], hnew[4*j+1], hnew[4*j+2], hnew[4*j+3]);
        }
        // gather inputs for step l+1: seq[l+1] = X[:, 10+l, conn]
        if (l < LL - 1) {
            int bb = tid >> 4, kk2 = tid & 15;
            xg2[kk2*HST + bb] =
                X[((size_t)(b0c + bb) * TT + (10 + l)) * PP + cidx[kk2]];
        }
        // finalize pred for step l (psum visible post-barrier)
        if (tid < 32) {
            int gg = tid >> 4, bidx = tid & 15;
            float s = 0.0f;
            #pragma unroll
            for (int w = 0; w < 8; w++) s += psum[gg][w][bidx];
            pred[((size_t)(p*BB + b0c + gg*16 + bidx)) * LL + l] = s + blv;
        }
        __syncthreads();   // hs2/xg2 writes + finalize visible before next compute
    }
}

extern "C" void kernel_launch(void* const* d_in, const int* in_sizes, int n_in,
                              void* d_out, int out_size)
{
    const float* X         = (const float*)d_in[0];
    const int*   conn_idx  = (const int*)  d_in[1];
    const float* W_ih_left = (const float*)d_in[2];
    const float* W_hh_left = (const float*)d_in[3];
    const float* b_ih_left = (const float*)d_in[4];
    const float* b_hh_left = (const float*)d_in[5];
    const float* W_ih_1    = (const float*)d_in[6];
    // d_in[7] = W_hh_1: unused (hidden state is 0 for gru_1's single step)
    const float* b_ih_1    = (const float*)d_in[8];
    const float* b_hh_1    = (const float*)d_in[9];
    const float* W_mu      = (const float*)d_in[10];
    const float* b_mu      = (const float*)d_in[11];
    const float* W_std     = (const float*)d_in[12];
    const float* b_std     = (const float*)d_in[13];
    const float* W_mean    = (const float*)d_in[14];
    const float* b_mean    = (const float*)d_in[15];
    const float* W_disp    = (const float*)d_in[16];
    const float* b_disp    = (const float*)d_in[17];
    const float* W_ih_nets = (const float*)d_in[18];
    const float* W_hh_nets = (const float*)d_in[19];
    const float* b_ih_nets = (const float*)d_in[20];
    const float* b_hh_nets = (const float*)d_in[21];
    const float* W_lin     = (const float*)d_in[22];
    const float* b_lin     = (const float*)d_in[23];
    const float* z_noise   = (const float*)d_in[24];

    float* out = (float*)d_out;
    float* pred       = out;
    float* out_logvar = out + 409600;
    float* out_mu     = out + 409600 + 16384;
    float* out_mean   = out + 409600 + 2*16384;
    float* out_disp   = out + 409600 + 2*16384 + 4096;

    float *wthh, *wtih, *wtenc;
    cudaGetSymbolAddress((void**)&wthh,  g_WThh);
    cudaGetSymbolAddress((void**)&wtih,  g_WTih);
    cudaGetSymbolAddress((void**)&wtenc, g_WTenc);

    dim3 tb(32, 8);

    // Launch 0: all 7 encoder-weight transposes fused
    EncT7 e;
    e.in[0] = W_hh_left; e.out[0] = wtenc + OFF_HHL;  e.R[0] = 768; e.C[0] = 256;
    e.in[1] = W_ih_left; e.out[1] = wtenc + OFF_IHL;  e.R[1] = 768; e.C[1] = 64;
    e.in[2] = W_ih_1;    e.out[2] = wtenc + OFF_IH1;  e.R[2] = 768; e.C[2] = 256;
    e.in[3] = W_mu;      e.out[3] = wtenc + OFF_MU;   e.R[3] = 256; e.C[3] = 256;
    e.in[4] = W_std;     e.out[4] = wtenc + OFF_STD;  e.R[4] = 256; e.C[4] = 256;
    e.in[5] = W_mean;    e.out[5] = wtenc + OFF_MEAN; e.R[5] = 64;  e.C[5] = 256;
    e.in[6] = W_disp;    e.out[6] = wtenc + OFF_DISP; e.R[6] = 64;  e.C[6] = 256;
    transpose_multi7<<<dim3(8, 24, 7), tb>>>(e);

    // Launch 1: encoder (needs launch 0)
    encoder_kernel<<<BB, 256>>>(
        X, b_ih_left, b_hh_left, b_ih_1, b_hh_1,
        b_mu, b_std, b_mean, b_disp, z_noise,
        out_logvar, out_mu, out_mean, out_disp);

    // Launch 2: nets weight transposes fused (hh: z<64, ih: z>=64)
    transpose_nets<<<dim3(8, 24, 2*PP), tb>>>(W_hh_nets, W_ih_nets, wthh, wtih);

    // Launch 3: nets (profiled slot: 2 harness launches + ours -> overall #5)
    nets_kernel<<<dim3(PP, BB/32), 512>>>(
        X, conn_idx, b_ih_nets, b_hh_nets, W_lin, b_lin, pred);
}

// round 10
// speedup vs baseline: 2.2241x; 1.0084x over previous
#include <cuda_runtime.h>
#include <math.h>

// Problem dims
#define BB 64     // batch
#define TT 110    // timesteps
#define PP 64     // series
#define HH 256    // hidden
#define KK 16     // connections
#define LL 100    // nets seq length

typedef unsigned long long u64;

// Output layout (tuple concat, all f32):
//   pred   (P,B,L,1) : 409600  @ 0
//   logvar (B,H)     : 16384   @ 409600
//   mu     (B,H)     : 16384   @ 425984
//   mean   (B,P)     : 4096    @ 442368
//   disp   (B,P)     : 4096    @ 446464

__device__ float g_z[BB * HH];                       // latent z scratch
__device__ float g_WThh[(size_t)PP * HH * 768];      // 48MB: Whh_nets transposed [p][k][768]
__device__ float g_WTih[(size_t)PP * KK * 768];      // 3MB:  Wih_nets transposed [p][k][768]
__device__ float g_WTenc[606208];                    // encoder weights transposed

#define OFF_HHL  0        // W_hh_left^T  [256][768]
#define OFF_IHL  196608   // W_ih_left^T  [64][768]
#define OFF_IH1  245760   // W_ih_1^T     [256][768]
#define OFF_MU   442368   // W_mu^T       [256][256]
#define OFF_STD  507904   // W_std^T      [256][256]
#define OFF_MEAN 573440   // W_mean^T     [256][64]
#define OFF_DISP 589824   // W_disp^T     [256][64]

__device__ __forceinline__ u64 pk2(float x) {
    u64 r; asm("mov.b64 %0, {%1, %1};" : "=l"(r) : "f"(x)); return r;
}
__device__ __forceinline__ u64 ffma2(u64 a, u64 b, u64 c) {
    u64 d; asm("fma.rn.f32x2 %0, %1, %2, %3;" : "=l"(d) : "l"(a), "l"(b), "l"(c)); return d;
}
__device__ __forceinline__ void upk2(u64 a, float& lo, float& hi) {
    asm("mov.b64 {%0, %1}, %2;" : "=f"(lo), "=f"(hi) : "l"(a));
}
__device__ __forceinline__ float fsig(float x) {
    return __fdividef(1.0f, 1.0f + __expf(-x));
}
__device__ __forceinline__ float ftanh_(float x) {
    float e = __expf(fminf(fmaxf(2.0f * x, -80.0f), 80.0f));
    return __fdividef(e - 1.0f, e + 1.0f);
}

// ------------------------------------------------------------------
// Launch 0: fused transpose of all 7 encoder matrices (blockIdx.z = m)
// ------------------------------------------------------------------
struct EncT7 {
    const float* in[7];
    float*       out[7];
    int          R[7];
    int          C[7];
};
__global__ void transpose_multi7(EncT7 e)
{
    __shared__ float tile[32][33];
    const int m = blockIdx.z;
    const float* __restrict__ in = e.in[m];
    float* __restrict__ out = e.out[m];
    const int R = e.R[m], C = e.C[m];
    const int x = blockIdx.x * 32 + threadIdx.x;
    const int ybase = blockIdx.y * 32;
    #pragma unroll
    for (int j = threadIdx.y; j < 32; j += 8) {
        int y = ybase + j;
        if (x < C && y < R) tile[j][threadIdx.x] = in[(size_t)y * C + x];
    }
    __syncthreads();
    const int xo = ybase + threadIdx.x;
    const int yobase = blockIdx.x * 32;
    #pragma unroll
    for (int j = threadIdx.y; j < 32; j += 8) {
        int yo = yobase + j;
        if (yo < C && xo < R) out[(size_t)yo * R + xo] = tile[threadIdx.x][j];
    }
}

// ------------------------------------------------------------------
// Launch 2: fused transpose of nets weights.
// z in [0,64):   Whh_nets p=z   (768,256) -> [p][256][768]
// z in [64,128): Wih_nets p=z-64 (768,16) -> [p][16][768]
// ------------------------------------------------------------------
__global__ void transpose_nets(const float* __restrict__ Whh,
                               const float* __restrict__ Wih,
                               float* __restrict__ outhh,
                               float* __restrict__ outih)
{
    __shared__ float tile[32][33];
    const int z = blockIdx.z;
    const float* __restrict__ in;
    float* __restrict__ out;
    int C;
    if (z < PP) {
        in  = Whh   + (size_t)z * 768 * HH;
        out = outhh + (size_t)z * HH * 768;
        C = HH;
    } else {
        in  = Wih   + (size_t)(z - PP) * 768 * KK;
        out = outih + (size_t)(z - PP) * KK * 768;
        C = KK;
    }
    const int R = 768;
    const int x = blockIdx.x * 32 + threadIdx.x;
    const int ybase = blockIdx.y * 32;
    #pragma unroll
    for (int j = threadIdx.y; j < 32; j += 8) {
        int y = ybase + j;
        if (x < C && y < R) tile[j][threadIdx.x] = in[(size_t)y * C + x];
    }
    __syncthreads();
    const int xo = ybase + threadIdx.x;
    const int yobase = blockIdx.x * 32;
    #pragma unroll
    for (int j = threadIdx.y; j < 32; j += 8) {
        int yo = yobase + j;
        if (yo < C && xo < R) out[(size_t)yo * R + xo] = tile[threadIdx.x][j];
    }
}

// ------------------------------------------------------------------
// Launch 1: Encoder: gru_left (10 steps) -> gru_1 (1 step) -> heads + z
// ------------------------------------------------------------------
__global__ void __launch_bounds__(256) encoder_kernel(
    const float* __restrict__ X,
    const float* __restrict__ bih_l, const float* __restrict__ bhh_l,
    const float* __restrict__ bih1,  const float* __restrict__ bhh1,
    const float* __restrict__ bmu,   const float* __restrict__ bstd,
    const float* __restrict__ bmean, const float* __restrict__ bdisp,
    const float* __restrict__ z_noise,
    float* __restrict__ out_logvar, float* __restrict__ out_mu,
    float* __restrict__ out_mean,   float* __restrict__ out_disp)
{
    const int b = blockIdx.x;
    const int t = threadIdx.x;
    __shared__ float hs[HH];
    __shared__ float xs[PP];
    hs[t] = 0.0f;

    const float bir = bih_l[t]        + bhh_l[t];
    const float biz = bih_l[HH + t]   + bhh_l[HH + t];
    const float bin = bih_l[2*HH + t];
    const float bhn = bhh_l[2*HH + t];
    const float* __restrict__ Wh = g_WTenc + OFF_HHL;
    const float* __restrict__ Wi = g_WTenc + OFF_IHL;
    __syncthreads();

    for (int s = 0; s < 10; s++) {
        if (t < PP) xs[t] = X[((size_t)b * TT + s) * PP + t];
        __syncthreads();
        float ar = bir, az = biz, an = bin, gn = bhn;
        #pragma unroll 4
        for (int k = 0; k < HH; k++) {
            float hk = hs[k];
            ar += hk * Wh[k*768 + t];
            az += hk * Wh[k*768 + 256 + t];
            gn += hk * Wh[k*768 + 512 + t];
        }
        #pragma unroll 4
        for (int k = 0; k < PP; k++) {
            float xk = xs[k];
            ar += xk * Wi[k*768 + t];
            az += xk * Wi[k*768 + 256 + t];
            an += xk * Wi[k*768 + 512 + t];
        }
        float r  = fsig(ar);
        float zz = fsig(az);
        float n  = ftanh_(an + r * gn);
        float hnew = (1.0f - zz) * n + zz * hs[t];
        __syncthreads();
        hs[t] = hnew;
        __syncthreads();
    }

    {
        const float* __restrict__ W1 = g_WTenc + OFF_IH1;
        float ar = bih1[t]        + bhh1[t];
        float az = bih1[HH + t]   + bhh1[HH + t];
        float an = bih1[2*HH + t];
        float gn = bhh1[2*HH + t];
        #pragma unroll 4
        for (int k = 0; k < HH; k++) {
            float hk = hs[k];
            ar += hk * W1[k*768 + t];
            az += hk * W1[k*768 + 256 + t];
            an += hk * W1[k*768 + 512 + t];
        }
        float r  = fsig(ar);
        float zz = fsig(az);
        float n  = ftanh_(an + r * gn);
        float h1 = (1.0f - zz) * n;
        __syncthreads();
        hs[t] = h1;
        __syncthreads();
    }

    {
        float mu = bmu[t], lv = bstd[t];
        const float* __restrict__ Wm = g_WTenc + OFF_MU;
        const float* __restrict__ Ws = g_WTenc + OFF_STD;
        #pragma unroll 4
        for (int k = 0; k < HH; k++) {
            float hk = hs[k];
            mu += hk * Wm[k*256 + t];
            lv += hk * Ws[k*256 + t];
        }
        out_mu[b*HH + t]     = mu;
        out_logvar[b*HH + t] = lv;
        g_z[b*HH + t] = mu + expf(0.5f * lv) * z_noise[b*HH + t];

        if (t < PP) {
            float m = bmean[t], d = bdisp[t];
            const float* __restrict__ Wme = g_WTenc + OFF_MEAN;
            const float* __restrict__ Wd  = g_WTenc + OFF_DISP;
            #pragma unroll 4
            for (int k = 0; k < HH; k++) {
                float hk = hs[k];
                m += hk * Wme[k*64 + t];
                d += hk * Wd[k*64 + t];
            }
            m = expf(m);
            m = fminf(fmaxf(m, 1e-5f), 1e6f);
            d = log1pf(expf(d));
            d = fminf(fmaxf(d, 1e-4f), 1e4f);
            out_mean[b*PP + t] = m;
            out_disp[b*PP + t] = d;
        }
    }
}

// ------------------------------------------------------------------
// Launch 3: Per-series GRU nets — R9 baseline + 8k weight-preload chunks.
// grid (64, 2), 512 threads = 2 groups x 256 units, 1 CTA/SM.
// Thread = 1 hidden unit x 16 batches; f32x2 packed accumulators.
// Hidden loop: chunks of 8 k; phase 1 preloads 24 weight scalars
// (registers), phase 2 runs 192 FFMA2 — covers next chunk's L2 latency.
// ------------------------------------------------------------------
#define BT 16
#define HST 36                 // hs row stride (32 batches + 4 pad)

__global__ void __launch_bounds__(512, 1) nets_kernel(
    const float* __restrict__ X,
    const int*   __restrict__ conn_idx,
    const float* __restrict__ bih,   // (P, 768)
    const float* __restrict__ bhh,   // (P, 768)
    const float* __restrict__ Wlin,  // (P, 1, 256)
    const float* __restrict__ blin,  // (P, 1)
    float* __restrict__ pred)        // (P, B, L, 1)
{
    const int p    = blockIdx.x;
    const int b0c  = blockIdx.y * 32;
    const int tid  = threadIdx.x;
    const int g    = tid >> 8;        // batch-group 0/1 (16 batches each)
    const int t    = tid & 255;       // hidden unit
    const int g16  = g << 4;
    const int lane = tid & 31;
    const int wg   = (tid >> 5) & 7;  // warp within group

    __shared__ __align__(16) float hs2[HH * HST];   // [k][32b]
    __shared__ __align__(16) float xg2[KK * HST];   // [k][32b]
    __shared__ float psum[2][8][16];
    __shared__ int   cidx[KK];

    if (tid < KK) cidx[tid] = conn_idx[p*KK + tid];
    for (int i = tid; i < KK*HST; i += 512) xg2[i] = 0.0f;  // step 0 = zero row
    #pragma unroll
    for (int j = 0; j < BT; j++)
        hs2[t*HST + g16 + j] = g_z[(size_t)(b0c + g16 + j) * HH + t];

    const size_t pb = (size_t)p * 768;
    const u64 brc2 = pk2(bih[pb + t]       + bhh[pb + t]);
    const u64 bzc2 = pk2(bih[pb + 256 + t] + bhh[pb + 256 + t]);
    const u64 bin2 = pk2(bih[pb + 512 + t]);
    const u64 bhn2 = pk2(bhh[pb + 512 + t]);
    const float wl  = Wlin[(size_t)p * HH + t];
    const float blv = blin[p];
    const float* __restrict__ Whp = g_WThh + (size_t)p * HH * 768 + t;  // [k][768]
    const float* __restrict__ Wip = g_WTih + (size_t)p * KK * 768 + t;  // [k][768]

    __syncthreads();

    for (int l = 0; l < LL; l++) {
        u64 ar2[8], az2[8], gi2[8], gh2[8];
        #pragma unroll
        for (int q = 0; q < 8; q++) { ar2[q]=brc2; az2[q]=bzc2; gi2[q]=bin2; gh2[q]=bhn2; }

        // input contribution (K = 16)
        #pragma unroll
        for (int k = 0; k < KK; k++) {
            const float* r_ = Wip + (size_t)k * 768;
            const u64 wr = pk2(r_[0]);
            const u64 wz = pk2(r_[256]);
            const u64 wn = pk2(r_[512]);
            const ulonglong2* hp =
                reinterpret_cast<const ulonglong2*>(&xg2[k*HST + g16]);
            #pragma unroll
            for (int q = 0; q < 4; q++) {
                ulonglong2 hv = hp[q];
                ar2[2*q]   = ffma2(hv.x, wr, ar2[2*q]);
                az2[2*q]   = ffma2(hv.x, wz, az2[2*q]);
                gi2[2*q]   = ffma2(hv.x, wn, gi2[2*q]);
                ar2[2*q+1] = ffma2(hv.y, wr, ar2[2*q+1]);
                az2[2*q+1] = ffma2(hv.y, wz, az2[2*q+1]);
                gi2[2*q+1] = ffma2(hv.y, wn, gi2[2*q+1]);
            }
        }

        // hidden contribution (H = 256) — chunks of 8 k:
        // phase 1 preloads 24 weight scalars; phase 2 is 192 FFMA2.
        #pragma unroll 1
        for (int kk = 0; kk < HH; kk += 8) {
            float wrf[8], wzf[8], wnf[8];
            #pragma unroll
            for (int j = 0; j < 8; j++) {
                const float* r_ = Whp + (size_t)(kk + j) * 768;
                wrf[j] = r_[0];
                wzf[j] = r_[256];
                wnf[j] = r_[512];
            }
            #pragma unroll
            for (int j = 0; j < 8; j++) {
                const u64 wr = pk2(wrf[j]);
                const u64 wz = pk2(wzf[j]);
                const u64 wn = pk2(wnf[j]);
                const ulonglong2* hp =
                    reinterpret_cast<const ulonglong2*>(&hs2[(kk + j)*HST + g16]);
                #pragma unroll
                for (int q = 0; q < 4; q++) {
                    ulonglong2 hv = hp[q];
                    ar2[2*q]   = ffma2(hv.x, wr, ar2[2*q]);
                    az2[2*q]   = ffma2(hv.x, wz, az2[2*q]);
                    gh2[2*q]   = ffma2(hv.x, wn, gh2[2*q]);
                    ar2[2*q+1] = ffma2(hv.y, wr, ar2[2*q+1]);
                    az2[2*q+1] = ffma2(hv.y, wz, az2[2*q+1]);
                    gh2[2*q+1] = ffma2(hv.y, wn, gh2[2*q+1]);
                }
            }
        }

        // old h for the z-gate mix (read pre-barrier)
        float hold[16];
        #pragma unroll
        for (int j = 0; j < 4; j++) {
            float4 hv = *reinterpret_cast<const float4*>(&hs2[t*HST + g16 + 4*j]);
            hold[4*j]   = hv.x; hold[4*j+1] = hv.y;
            hold[4*j+2] = hv.z; hold[4*j+3] = hv.w;
        }

        float hnew[16];
        #pragma unroll
        for (int q = 0; q < 8; q++) {
            float a0,a1,z0,z1,i0,i1,n0,n1;
            upk2(ar2[q], a0, a1);
            upk2(az2[q], z0, z1);
            upk2(gi2[q], i0, i1);
            upk2(gh2[q], n0, n1);
            float r0 = fsig(a0), r1 = fsig(a1);
            float zz0 = fsig(z0), zz1 = fsig(z1);
            float nn0 = ftanh_(i0 + r0 * n0);
            float nn1 = ftanh_(i1 + r1 * n1);
            hnew[2*q]   = (1.0f - zz0) * nn0 + zz0 * hold[2*q];
            hnew[2*q+1] = (1.0f - zz1) * nn1 + zz1 * hold[2*q+1];
        }

        // pred partials from registers: warp-reduce per batch
        #pragma unroll
        for (int i = 0; i < 16; i++) {
            float v = fmaxf(hnew[i], 0.0f) * wl;
            v += __shfl_xor_sync(0xffffffffu, v, 16);
            v += __shfl_xor_sync(0xffffffffu, v, 8);
            v += __shfl_xor_sync(0xffffffffu, v, 4);
            v += __shfl_xor_sync(0xffffffffu, v, 2);
            v += __shfl_xor_sync(0xffffffffu, v, 1);
            if (lane == i) psum[g][wg][i] = v;
        }

        __syncthreads();   // all reads of old hs2/xg2 + psum writes complete

        // commit new hidden state (k-major)
        #pragma unroll
        for (int j = 0; j < 4; j++) {
            *reinterpret_cast<float4*>(&hs2[t*HST + g16 + 4*j]) =
                make_float4(hnew[4*j], hnew[4*j+1], hnew[4*j+2], hnew[4*j+3]);
        }
        // gather inputs for step l+1: seq[l+1] = X[:, 10+l, conn]
        if (l < LL - 1) {
            int bb = tid >> 4, kk2 = tid & 15;
            xg2[kk2*HST + bb] =
                X[((size_t)(b0c + bb) * TT + (10 + l)) * PP + cidx[kk2]];
        }
        // finalize pred for step l (psum visible post-barrier)
        if (tid < 32) {
            int gg = tid >> 4, bidx = tid & 15;
            float s = 0.0f;
            #pragma unroll
            for (int w = 0; w < 8; w++) s += psum[gg][w][bidx];
            pred[((size_t)(p*BB + b0c + gg*16 + bidx)) * LL + l] = s + blv;
        }
        __syncthreads();   // hs2/xg2 writes + finalize visible before next compute
    }
}

extern "C" void kernel_launch(void* const* d_in, const int* in_sizes, int n_in,
                              void* d_out, int out_size)
{
    const float* X         = (const float*)d_in[0];
    const int*   conn_idx  = (const int*)  d_in[1];
    const float* W_ih_left = (const float*)d_in[2];
    const float* W_hh_left = (const float*)d_in[3];
    const float* b_ih_left = (const float*)d_in[4];
    const float* b_hh_left = (const float*)d_in[5];
    const float* W_ih_1    = (const float*)d_in[6];
    // d_in[7] = W_hh_1: unused (hidden state is 0 for gru_1's single step)
    const float* b_ih_1    = (const float*)d_in[8];
    const float* b_hh_1    = (const float*)d_in[9];
    const float* W_mu      = (const float*)d_in[10];
    const float* b_mu      = (const float*)d_in[11];
    const float* W_std     = (const float*)d_in[12];
    const float* b_std     = (const float*)d_in[13];
    const float* W_mean    = (const float*)d_in[14];
    const float* b_mean    = (const float*)d_in[15];
    const float* W_disp    = (const float*)d_in[16];
    const float* b_disp    = (const float*)d_in[17];
    const float* W_ih_nets = (const float*)d_in[18];
    const float* W_hh_nets = (const float*)d_in[19];
    const float* b_ih_nets = (const float*)d_in[20];
    const float* b_hh_nets = (const float*)d_in[21];
    const float* W_lin     = (const float*)d_in[22];
    const float* b_lin     = (const float*)d_in[23];
    const float* z_noise   = (const float*)d_in[24];

    float* out = (float*)d_out;
    float* pred       = out;
    float* out_logvar = out + 409600;
    float* out_mu     = out + 409600 + 16384;
    float* out_mean   = out + 409600 + 2*16384;
    float* out_disp   = out + 409600 + 2*16384 + 4096;

    float *wthh, *wtih, *wtenc;
    cudaGetSymbolAddress((void**)&wthh,  g_WThh);
    cudaGetSymbolAddress((void**)&wtih,  g_WTih);
    cudaGetSymbolAddress((void**)&wtenc, g_WTenc);

    dim3 tb(32, 8);

    // Launch 0: all 7 encoder-weight transposes fused
    EncT7 e;
    e.in[0] = W_hh_left; e.out[0] = wtenc + OFF_HHL;  e.R[0] = 768; e.C[0] = 256;
    e.in[1] = W_ih_left; e.out[1] = wtenc + OFF_IHL;  e.R[1] = 768; e.C[1] = 64;
    e.in[2] = W_ih_1;    e.out[2] = wtenc + OFF_IH1;  e.R[2] = 768; e.C[2] = 256;
    e.in[3] = W_mu;      e.out[3] = wtenc + OFF_MU;   e.R[3] = 256; e.C[3] = 256;
    e.in[4] = W_std;     e.out[4] = wtenc + OFF_STD;  e.R[4] = 256; e.C[4] = 256;
    e.in[5] = W_mean;    e.out[5] = wtenc + OFF_MEAN; e.R[5] = 64;  e.C[5] = 256;
    e.in[6] = W_disp;    e.out[6] = wtenc + OFF_DISP; e.R[6] = 64;  e.C[6] = 256;
    transpose_multi7<<<dim3(8, 24, 7), tb>>>(e);

    // Launch 1: encoder (needs launch 0)
    encoder_kernel<<<BB, 256>>>(
        X, b_ih_left, b_hh_left, b_ih_1, b_hh_1,
        b_mu, b_std, b_mean, b_disp, z_noise,
        out_logvar, out_mu, out_mean, out_disp);

    // Launch 2: nets weight transposes fused (hh: z<64, ih: z>=64)
    transpose_nets<<<dim3(8, 24, 2*PP), tb>>>(W_hh_nets, W_ih_nets, wthh, wtih);

    // Launch 3: nets (profiled slot: 2 harness launches + ours -> overall #5)
    nets_kernel<<<dim3(PP, BB/32), 512>>>(
        X, conn_idx, b_ih_nets, b_hh_nets, W_lin, b_lin, pred);
}

// round 11
// speedup vs baseline: 2.3069x; 1.0373x over previous
#include <cuda_runtime.h>
#include <math.h>

// Problem dims
#define BB 64     // batch
#define TT 110    // timesteps
#define PP 64     // series
#define HH 256    // hidden
#define KK 16     // connections
#define LL 100    // nets seq length

typedef unsigned long long u64;

// Output layout (tuple concat, all f32):
//   pred   (P,B,L,1) : 409600  @ 0
//   logvar (B,H)     : 16384   @ 409600
//   mu     (B,H)     : 16384   @ 425984
//   mean   (B,P)     : 4096    @ 442368
//   disp   (B,P)     : 4096    @ 446464

__device__ float g_z[BB * HH];                       // latent z scratch
__device__ float g_WThh[(size_t)PP * HH * 768];      // 48MB: Whh_nets transposed [p][k][768]
__device__ float g_WTih[(size_t)PP * KK * 768];      // 3MB:  Wih_nets transposed [p][k][768]
__device__ float g_WTenc[606208];                    // encoder weights transposed

#define OFF_HHL  0        // W_hh_left^T  [256][768]
#define OFF_IHL  196608   // W_ih_left^T  [64][768]
#define OFF_IH1  245760   // W_ih_1^T     [256][768]
#define OFF_MU   442368   // W_mu^T       [256][256]
#define OFF_STD  507904   // W_std^T      [256][256]
#define OFF_MEAN 573440   // W_mean^T     [256][64]
#define OFF_DISP 589824   // W_disp^T     [256][64]

__device__ __forceinline__ u64 pk2(float x) {
    u64 r; asm("mov.b64 %0, {%1, %1};" : "=l"(r) : "f"(x)); return r;
}
__device__ __forceinline__ u64 ffma2(u64 a, u64 b, u64 c) {
    u64 d; asm("fma.rn.f32x2 %0, %1, %2, %3;" : "=l"(d) : "l"(a), "l"(b), "l"(c)); return d;
}
__device__ __forceinline__ void upk2(u64 a, float& lo, float& hi) {
    asm("mov.b64 {%0, %1}, %2;" : "=f"(lo), "=f"(hi) : "l"(a));
}
__device__ __forceinline__ float fsig(float x) {
    return __fdividef(1.0f, 1.0f + __expf(-x));
}
__device__ __forceinline__ float ftanh_(float x) {
    float e = __expf(fminf(fmaxf(2.0f * x, -80.0f), 80.0f));
    return __fdividef(e - 1.0f, e + 1.0f);
}

// ------------------------------------------------------------------
// Launch 0: fused transpose of all 7 encoder matrices (blockIdx.z = m)
// ------------------------------------------------------------------
struct EncT7 {
    const float* in[7];
    float*       out[7];
    int          R[7];
    int          C[7];
};
__global__ void transpose_multi7(EncT7 e)
{
    __shared__ float tile[32][33];
    const int m = blockIdx.z;
    const float* __restrict__ in = e.in[m];
    float* __restrict__ out = e.out[m];
    const int R = e.R[m], C = e.C[m];
    const int x = blockIdx.x * 32 + threadIdx.x;
    const int ybase = blockIdx.y * 32;
    #pragma unroll
    for (int j = threadIdx.y; j < 32; j += 8) {
        int y = ybase + j;
        if (x < C && y < R) tile[j][threadIdx.x] = in[(size_t)y * C + x];
    }
    __syncthreads();
    const int xo = ybase + threadIdx.x;
    const int yobase = blockIdx.x * 32;
    #pragma unroll
    for (int j = threadIdx.y; j < 32; j += 8) {
        int yo = yobase + j;
        if (yo < C && xo < R) out[(size_t)yo * R + xo] = tile[threadIdx.x][j];
    }
}

// ------------------------------------------------------------------
// Launch 2: fused transpose of nets weights.
// z in [0,64):   Whh_nets p=z   (768,256) -> [p][256][768]
// z in [64,128): Wih_nets p=z-64 (768,16) -> [p][16][768]
// ------------------------------------------------------------------
__global__ void transpose_nets(const float* __restrict__ Whh,
                               const float* __restrict__ Wih,
                               float* __restrict__ outhh,
                               float* __restrict__ outih)
{
    __shared__ float tile[32][33];
    const int z = blockIdx.z;
    const float* __restrict__ in;
    float* __restrict__ out;
    int C;
    if (z < PP) {
        in  = Whh   + (size_t)z * 768 * HH;
        out = outhh + (size_t)z * HH * 768;
        C = HH;
    } else {
        in  = Wih   + (size_t)(z - PP) * 768 * KK;
        out = outih + (size_t)(z - PP) * KK * 768;
        C = KK;
    }
    const int R = 768;
    const int x = blockIdx.x * 32 + threadIdx.x;
    const int ybase = blockIdx.y * 32;
    #pragma unroll
    for (int j = threadIdx.y; j < 32; j += 8) {
        int y = ybase + j;
        if (x < C && y < R) tile[j][threadIdx.x] = in[(size_t)y * C + x];
    }
    __syncthreads();
    const int xo = ybase + threadIdx.x;
    const int yobase = blockIdx.x * 32;
    #pragma unroll
    for (int j = threadIdx.y; j < 32; j += 8) {
        int yo = yobase + j;
        if (yo < C && xo < R) out[(size_t)yo * R + xo] = tile[threadIdx.x][j];
    }
}

// ------------------------------------------------------------------
// Launch 1: Encoder: gru_left (10 steps) -> gru_1 (1 step) -> heads + z
// ------------------------------------------------------------------
__global__ void __launch_bounds__(256) encoder_kernel(
    const float* __restrict__ X,
    const float* __restrict__ bih_l, const float* __restrict__ bhh_l,
    const float* __restrict__ bih1,  const float* __restrict__ bhh1,
    const float* __restrict__ bmu,   const float* __restrict__ bstd,
    const float* __restrict__ bmean, const float* __restrict__ bdisp,
    const float* __restrict__ z_noise,
    float* __restrict__ out_logvar, float* __restrict__ out_mu,
    float* __restrict__ out_mean,   float* __restrict__ out_disp)
{
    const int b = blockIdx.x;
    const int t = threadIdx.x;
    __shared__ float hs[HH];
    __shared__ float xs[PP];
    hs[t] = 0.0f;

    const float bir = bih_l[t]        + bhh_l[t];
    const float biz = bih_l[HH + t]   + bhh_l[HH + t];
    const float bin = bih_l[2*HH + t];
    const float bhn = bhh_l[2*HH + t];
    const float* __restrict__ Wh = g_WTenc + OFF_HHL;
    const float* __restrict__ Wi = g_WTenc + OFF_IHL;
    __syncthreads();

    for (int s = 0; s < 10; s++) {
        if (t < PP) xs[t] = X[((size_t)b * TT + s) * PP + t];
        __syncthreads();
        float ar = bir, az = biz, an = bin, gn = bhn;
        #pragma unroll 4
        for (int k = 0; k < HH; k++) {
            float hk = hs[k];
            ar += hk * Wh[k*768 + t];
            az += hk * Wh[k*768 + 256 + t];
            gn += hk * Wh[k*768 + 512 + t];
        }
        #pragma unroll 4
        for (int k = 0; k < PP; k++) {
            float xk = xs[k];
            ar += xk * Wi[k*768 + t];
            az += xk * Wi[k*768 + 256 + t];
            an += xk * Wi[k*768 + 512 + t];
        }
        float r  = fsig(ar);
        float zz = fsig(az);
        float n  = ftanh_(an + r * gn);
        float hnew = (1.0f - zz) * n + zz * hs[t];
        __syncthreads();
        hs[t] = hnew;
        __syncthreads();
    }

    {
        const float* __restrict__ W1 = g_WTenc + OFF_IH1;
        float ar = bih1[t]        + bhh1[t];
        float az = bih1[HH + t]   + bhh1[HH + t];
        float an = bih1[2*HH + t];
        float gn = bhh1[2*HH + t];
        #pragma unroll 4
        for (int k = 0; k < HH; k++) {
            float hk = hs[k];
            ar += hk * W1[k*768 + t];
            az += hk * W1[k*768 + 256 + t];
            an += hk * W1[k*768 + 512 + t];
        }
        float r  = fsig(ar);
        float zz = fsig(az);
        float n  = ftanh_(an + r * gn);
        float h1 = (1.0f - zz) * n;
        __syncthreads();
        hs[t] = h1;
        __syncthreads();
    }

    {
        float mu = bmu[t], lv = bstd[t];
        const float* __restrict__ Wm = g_WTenc + OFF_MU;
        const float* __restrict__ Ws = g_WTenc + OFF_STD;
        #pragma unroll 4
        for (int k = 0; k < HH; k++) {
            float hk = hs[k];
            mu += hk * Wm[k*256 + t];
            lv += hk * Ws[k*256 + t];
        }
        out_mu[b*HH + t]     = mu;
        out_logvar[b*HH + t] = lv;
        g_z[b*HH + t] = mu + expf(0.5f * lv) * z_noise[b*HH + t];

        if (t < PP) {
            float m = bmean[t], d = bdisp[t];
            const float* __restrict__ Wme = g_WTenc + OFF_MEAN;
            const float* __restrict__ Wd  = g_WTenc + OFF_DISP;
            #pragma unroll 4
            for (int k = 0; k < HH; k++) {
                float hk = hs[k];
                m += hk * Wme[k*64 + t];
                d += hk * Wd[k*64 + t];
            }
            m = expf(m);
            m = fminf(fmaxf(m, 1e-5f), 1e6f);
            d = log1pf(expf(d));
            d = fminf(fmaxf(d, 1e-4f), 1e4f);
            out_mean[b*PP + t] = m;
            out_disp[b*PP + t] = d;
        }
    }
}

// ------------------------------------------------------------------
// Launch 3: Per-series GRU nets — R10 hot loop, split into 256-thread
// CTAs with 2 CTAs/SM (private barriers -> cross-CTA latency hiding).
// grid (64, 4); thread = 1 hidden unit x 16 batches; f32x2 accums.
// Register cap stays 128 (65536 / 512 threads per SM): no spills.
// Hidden loop: chunks of 8 k; preload 24 weight scalars, then 192 FFMA2.
// ------------------------------------------------------------------
#define BT 16
#define HST 20                 // hs row stride (16 batches + 4 pad)

__global__ void __launch_bounds__(256, 2) nets_kernel(
    const float* __restrict__ X,
    const int*   __restrict__ conn_idx,
    const float* __restrict__ bih,   // (P, 768)
    const float* __restrict__ bhh,   // (P, 768)
    const float* __restrict__ Wlin,  // (P, 1, 256)
    const float* __restrict__ blin,  // (P, 1)
    float* __restrict__ pred)        // (P, B, L, 1)
{
    const int p    = blockIdx.x;
    const int b0c  = blockIdx.y * BT;
    const int tid  = threadIdx.x;
    const int t    = tid;             // hidden unit
    const int lane = tid & 31;
    const int wg   = tid >> 5;        // warp 0..7

    __shared__ __align__(16) float hs2[HH * HST];   // [k][16b]
    __shared__ __align__(16) float xg2[KK * HST];   // [k][16b]
    __shared__ float psum[8][16];
    __shared__ int   cidx[KK];

    if (tid < KK) cidx[tid] = conn_idx[p*KK + tid];
    for (int i = tid; i < KK*HST; i += 256) xg2[i] = 0.0f;  // step 0 = zero row
    #pragma unroll
    for (int j = 0; j < BT; j++)
        hs2[t*HST + j] = g_z[(size_t)(b0c + j) * HH + t];

    const size_t pb = (size_t)p * 768;
    const u64 brc2 = pk2(bih[pb + t]       + bhh[pb + t]);
    const u64 bzc2 = pk2(bih[pb + 256 + t] + bhh[pb + 256 + t]);
    const u64 bin2 = pk2(bih[pb + 512 + t]);
    const u64 bhn2 = pk2(bhh[pb + 512 + t]);
    const float wl  = Wlin[(size_t)p * HH + t];
    const float blv = blin[p];
    const float* __restrict__ Whp = g_WThh + (size_t)p * HH * 768 + t;  // [k][768]
    const float* __restrict__ Wip = g_WTih + (size_t)p * KK * 768 + t;  // [k][768]

    __syncthreads();

    for (int l = 0; l < LL; l++) {
        u64 ar2[8], az2[8], gi2[8], gh2[8];
        #pragma unroll
        for (int q = 0; q < 8; q++) { ar2[q]=brc2; az2[q]=bzc2; gi2[q]=bin2; gh2[q]=bhn2; }

        // input contribution (K = 16)
        #pragma unroll
        for (int k = 0; k < KK; k++) {
            const float* r_ = Wip + (size_t)k * 768;
            const u64 wr = pk2(r_[0]);
            const u64 wz = pk2(r_[256]);
            const u64 wn = pk2(r_[512]);
            const ulonglong2* hp =
                reinterpret_cast<const ulonglong2*>(&xg2[k*HST]);
            #pragma unroll
            for (int q = 0; q < 4; q++) {
                ulonglong2 hv = hp[q];
                ar2[2*q]   = ffma2(hv.x, wr, ar2[2*q]);
                az2[2*q]   = ffma2(hv.x, wz, az2[2*q]);
                gi2[2*q]   = ffma2(hv.x, wn, gi2[2*q]);
                ar2[2*q+1] = ffma2(hv.y, wr, ar2[2*q+1]);
                az2[2*q+1] = ffma2(hv.y, wz, az2[2*q+1]);
                gi2[2*q+1] = ffma2(hv.y, wn, gi2[2*q+1]);
            }
        }

        // hidden contribution (H = 256) — chunks of 8 k:
        // phase 1 preloads 24 weight scalars; phase 2 is 192 FFMA2.
        #pragma unroll 1
        for (int kk = 0; kk < HH; kk += 8) {
            float wrf[8], wzf[8], wnf[8];
            #pragma unroll
            for (int j = 0; j < 8; j++) {
                const float* r_ = Whp + (size_t)(kk + j) * 768;
                wrf[j] = r_[0];
                wzf[j] = r_[256];
                wnf[j] = r_[512];
            }
            #pragma unroll
            for (int j = 0; j < 8; j++) {
                const u64 wr = pk2(wrf[j]);
                const u64 wz = pk2(wzf[j]);
                const u64 wn = pk2(wnf[j]);
                const ulonglong2* hp =
                    reinterpret_cast<const ulonglong2*>(&hs2[(kk + j)*HST]);
                #pragma unroll
                for (int q = 0; q < 4; q++) {
                    ulonglong2 hv = hp[q];
                    ar2[2*q]   = ffma2(hv.x, wr, ar2[2*q]);
                    az2[2*q]   = ffma2(hv.x, wz, az2[2*q]);
                    gh2[2*q]   = ffma2(hv.x, wn, gh2[2*q]);
                    ar2[2*q+1] = ffma2(hv.y, wr, ar2[2*q+1]);
                    az2[2*q+1] = ffma2(hv.y, wz, az2[2*q+1]);
                    gh2[2*q+1] = ffma2(hv.y, wn, gh2[2*q+1]);
                }
            }
        }

        // old h for the z-gate mix (read pre-barrier)
        float hold[16];
        #pragma unroll
        for (int j = 0; j < 4; j++) {
            float4 hv = *reinterpret_cast<const float4*>(&hs2[t*HST + 4*j]);
            hold[4*j]   = hv.x; hold[4*j+1] = hv.y;
            hold[4*j+2] = hv.z; hold[4*j+3] = hv.w;
        }

        float hnew[16];
        #pragma unroll
        for (int q = 0; q < 8; q++) {
            float a0,a1,z0,z1,i0,i1,n0,n1;
            upk2(ar2[q], a0, a1);
            upk2(az2[q], z0, z1);
            upk2(gi2[q], i0, i1);
            upk2(gh2[q], n0, n1);
            float r0 = fsig(a0), r1 = fsig(a1);
            float zz0 = fsig(z0), zz1 = fsig(z1);
            float nn0 = ftanh_(i0 + r0 * n0);
            float nn1 = ftanh_(i1 + r1 * n1);
            hnew[2*q]   = (1.0f - zz0) * nn0 + zz0 * hold[2*q];
            hnew[2*q+1] = (1.0f - zz1) * nn1 + zz1 * hold[2*q+1];
        }

        // pred partials from registers: warp-reduce per batch
        #pragma unroll
        for (int i = 0; i < 16; i++) {
            float v = fmaxf(hnew[i], 0.0f) * wl;
            v += __shfl_xor_sync(0xffffffffu, v, 16);
            v += __shfl_xor_sync(0xffffffffu, v, 8);
            v += __shfl_xor_sync(0xffffffffu, v, 4);
            v += __shfl_xor_sync(0xffffffffu, v, 2);
            v += __shfl_xor_sync(0xffffffffu, v, 1);
            if (lane == i) psum[wg][i] = v;
        }

        __syncthreads();   // all reads of old hs2/xg2 + psum writes complete

        // commit new hidden state (k-major)
        #pragma unroll
        for (int j = 0; j < 4; j++) {
            *reinterpret_cast<float4*>(&hs2[t*HST + 4*j]) =
                make_float4(hnew[4*j], hnew[4*j+1], hnew[4*j+2], hnew[4*j+3]);
        }
        // gather inputs for step l+1: seq[l+1] = X[:, 10+l, conn]
        if (l < LL - 1) {
            int bb = tid >> 4, kk2 = tid & 15;   // 256 threads = 16 b x 16 k
            xg2[kk2*HST + bb] =
                X[((size_t)(b0c + bb) * TT + (10 + l)) * PP + cidx[kk2]];
        }
        // finalize pred for step l (psum visible post-barrier)
        if (tid < 16) {
            float s = 0.0f;
            #pragma unroll
            for (int w = 0; w < 8; w++) s += psum[w][tid];
            pred[((size_t)(p*BB + b0c + tid)) * LL + l] = s + blv;
        }
        __syncthreads();   // hs2/xg2 writes + finalize visible before next compute
    }
}

extern "C" void kernel_launch(void* const* d_in, const int* in_sizes, int n_in,
                              void* d_out, int out_size)
{
    const float* X         = (const float*)d_in[0];
    const int*   conn_idx  = (const int*)  d_in[1];
    const float* W_ih_left = (const float*)d_in[2];
    const float* W_hh_left = (const float*)d_in[3];
    const float* b_ih_left = (const float*)d_in[4];
    const float* b_hh_left = (const float*)d_in[5];
    const float* W_ih_1    = (const float*)d_in[6];
    // d_in[7] = W_hh_1: unused (hidden state is 0 for gru_1's single step)
    const float* b_ih_1    = (const float*)d_in[8];
    const float* b_hh_1    = (const float*)d_in[9];
    const float* W_mu      = (const float*)d_in[10];
    const float* b_mu      = (const float*)d_in[11];
    const float* W_std     = (const float*)d_in[12];
    const float* b_std     = (const float*)d_in[13];
    const float* W_mean    = (const float*)d_in[14];
    const float* b_mean    = (const float*)d_in[15];
    const float* W_disp    = (const float*)d_in[16];
    const float* b_disp    = (const float*)d_in[17];
    const float* W_ih_nets = (const float*)d_in[18];
    const float* W_hh_nets = (const float*)d_in[19];
    const float* b_ih_nets = (const float*)d_in[20];
    const float* b_hh_nets = (const float*)d_in[21];
    const float* W_lin     = (const float*)d_in[22];
    const float* b_lin     = (const float*)d_in[23];
    const float* z_noise   = (const float*)d_in[24];

    float* out = (float*)d_out;
    float* pred       = out;
    float* out_logvar = out + 409600;
    float* out_mu     = out + 409600 + 16384;
    float* out_mean   = out + 409600 + 2*16384;
    float* out_disp   = out + 409600 + 2*16384 + 4096;

    float *wthh, *wtih, *wtenc;
    cudaGetSymbolAddress((void**)&wthh,  g_WThh);
    cudaGetSymbolAddress((void**)&wtih,  g_WTih);
    cudaGetSymbolAddress((void**)&wtenc, g_WTenc);

    dim3 tb(32, 8);

    // Launch 0: all 7 encoder-weight transposes fused
    EncT7 e;
    e.in[0] = W_hh_left; e.out[0] = wtenc + OFF_HHL;  e.R[0] = 768; e.C[0] = 256;
    e.in[1] = W_ih_left; e.out[1] = wtenc + OFF_IHL;  e.R[1] = 768; e.C[1] = 64;
    e.in[2] = W_ih_1;    e.out[2] = wtenc + OFF_IH1;  e.R[2] = 768; e.C[2] = 256;
    e.in[3] = W_mu;      e.out[3] = wtenc + OFF_MU;   e.R[3] = 256; e.C[3] = 256;
    e.in[4] = W_std;     e.out[4] = wtenc + OFF_STD;  e.R[4] = 256; e.C[4] = 256;
    e.in[5] = W_mean;    e.out[5] = wtenc + OFF_MEAN; e.R[5] = 64;  e.C[5] = 256;
    e.in[6] = W_disp;    e.out[6] = wtenc + OFF_DISP; e.R[6] = 64;  e.C[6] = 256;
    transpose_multi7<<<dim3(8, 24, 7), tb>>>(e);

    // Launch 1: encoder (needs launch 0)
    encoder_kernel<<<BB, 256>>>(
        X, b_ih_left, b_hh_left, b_ih_1, b_hh_1,
        b_mu, b_std, b_mean, b_disp, z_noise,
        out_logvar, out_mu, out_mean, out_disp);

    // Launch 2: nets weight transposes fused (hh: z<64, ih: z>=64)
    transpose_nets<<<dim3(8, 24, 2*PP), tb>>>(W_hh_nets, W_ih_nets, wthh, wtih);

    // Launch 3: nets (profiled slot)
    nets_kernel<<<dim3(PP, BB/BT), 256>>>(
        X, conn_idx, b_ih_nets, b_hh_nets, W_lin, b_lin, pred);
}